// round 3
// baseline (speedup 1.0000x reference)
#include <cuda_runtime.h>
#include <cuda_fp16.h>
#include <cstdint>
#include <cstddef>

// ---------------------------------------------------------------------------
// Problem constants
// ---------------------------------------------------------------------------
#define TT    512
#define BB    256
#define NIN   128      // NINP (127 input + 1 dt)
#define NH    512      // NHID
#define NGATE 2048     // 4*NHID
#define KTOT  640      // NIN + NH
#define NOUT  64

// Tiling: CTA = 64 rows x 64 cols, K chunks of 64. fp16-split (hi+lo planes).
#define ROWB   144            // smem row stride bytes (64 fp16 = 128B + 16B pad)
#define PLANE  (64 * ROWB)    // 9216 B, one 64x64 fp16 plane
#define STAGEB (4 * PLANE)    // Ahi,Alo,Whi,Wlo = 36864 B
#define DYN_SMEM (2 * STAGEB) // 73728 B
#define SK_CHUNKS 10          // 640/64
#define CLS_CHUNKS 8          // 512/64

// ---------------------------------------------------------------------------
// Device scratch
// ---------------------------------------------------------------------------
__device__ __half g_Xhi[(size_t)TT * BB * NIN];
__device__ __half g_Xlo[(size_t)TT * BB * NIN];
__device__ __half g_Whi[(size_t)NGATE * KTOT];   // permuted col 4j+g -> row
__device__ __half g_Wlo[(size_t)NGATE * KTOT];
__device__ __half g_Wchi[(size_t)NOUT * NH];
__device__ __half g_Wclo[(size_t)NOUT * NH];
__device__ float  g_bias[NGATE];                 // permuted b_ih+b_hh
__device__ __half g_Hhi[(size_t)(TT + 1) * BB * NH];  // slot s = h_{s-1}
__device__ __half g_Hlo[(size_t)(TT + 1) * BB * NH];
__device__ float  g_C[(size_t)BB * NH];

// ---------------------------------------------------------------------------
// Helpers
// ---------------------------------------------------------------------------
__device__ __forceinline__ uint32_t smem_u32(const void* p) {
    uint32_t a;
    asm("{ .reg .u64 t; cvta.to.shared.u64 t, %1; cvt.u32.u64 %0, t; }" : "=r"(a) : "l"(p));
    return a;
}

__device__ __forceinline__ void ldsm4(uint32_t addr, uint32_t r[4]) {
    asm volatile("ldmatrix.sync.aligned.m8n8.x4.shared.b16 {%0,%1,%2,%3}, [%4];"
                 : "=r"(r[0]), "=r"(r[1]), "=r"(r[2]), "=r"(r[3]) : "r"(addr));
}

__device__ __forceinline__ void mma16816(float c[4], const uint32_t a[4],
                                         uint32_t b0, uint32_t b1) {
    asm volatile("mma.sync.aligned.m16n8k16.row.col.f32.f16.f16.f32 "
                 "{%0,%1,%2,%3}, {%4,%5,%6,%7}, {%8,%9}, {%0,%1,%2,%3};"
                 : "+f"(c[0]), "+f"(c[1]), "+f"(c[2]), "+f"(c[3])
                 : "r"(a[0]), "r"(a[1]), "r"(a[2]), "r"(a[3]), "r"(b0), "r"(b1));
}

__device__ __forceinline__ void cpa16(uint32_t dst, const void* src) {
    asm volatile("cp.async.cg.shared.global [%0], [%1], 16;" :: "r"(dst), "l"(src));
}

__device__ __forceinline__ float fsigmoid(float x) {
    x = fminf(fmaxf(x, -30.f), 30.f);
    return 1.0f / (1.0f + __expf(-x));
}
__device__ __forceinline__ float ftanh(float x) {
    x = fminf(fmaxf(x, -15.f), 15.f);
    float e = __expf(-2.0f * x);
    return (1.0f - e) / (1.0f + e);
}

// Load one K=64 stage: A (64 x 64, hi+lo) + W (64 x 64, hi+lo) via cp.async.
__device__ __forceinline__ void load_stage(uint32_t dstbase, int tid,
                                           const __half* ahi, const __half* alo, int astr,
                                           const __half* whi, const __half* wlo, int wstr) {
#pragma unroll
    for (int i = 0; i < 8; i++) {
        int idx = tid + 128 * i;                 // 0..1023
        int plane = idx >> 9, rem = idx & 511, r = rem >> 3, ch = rem & 7;
        const __half* src = (plane ? alo : ahi) + (size_t)r * astr + ch * 8;
        cpa16(dstbase + plane * PLANE + r * ROWB + ch * 16, src);
    }
#pragma unroll
    for (int i = 0; i < 8; i++) {
        int idx = tid + 128 * i;
        int plane = idx >> 9, rem = idx & 511, r = rem >> 3, ch = rem & 7;
        const __half* src = (plane ? wlo : whi) + (size_t)r * wstr + ch * 8;
        cpa16(dstbase + 2 * PLANE + plane * PLANE + r * ROWB + ch * 16, src);
    }
    asm volatile("cp.async.commit_group;" ::: "memory");
}

// One K=64 chunk of MMA work for this warp (tile 32m x 32n).
__device__ __forceinline__ void compute_chunk(uint32_t sbase, int mwb, int nwb,
                                              uint32_t aoff, uint32_t boff,
                                              float c[2][4][4]) {
#pragma unroll
    for (int kk = 0; kk < 4; kk++) {
        uint32_t ahi[2][4], alo[2][4], bhi[2][4], blo[2][4];
#pragma unroll
        for (int mt = 0; mt < 2; mt++) {
            uint32_t base = sbase + (uint32_t)(mwb + mt * 16) * ROWB + kk * 32 + aoff;
            ldsm4(base, ahi[mt]);
            ldsm4(base + PLANE, alo[mt]);
        }
#pragma unroll
        for (int q = 0; q < 2; q++) {
            uint32_t base = sbase + 2 * PLANE + (uint32_t)(nwb + q * 16) * ROWB + kk * 32 + boff;
            ldsm4(base, bhi[q]);
            ldsm4(base + PLANE, blo[q]);
        }
        // three passes so dependent accumulations are 8 instructions apart
#pragma unroll
        for (int mt = 0; mt < 2; mt++)
#pragma unroll
            for (int j = 0; j < 4; j++)
                mma16816(c[mt][j], ahi[mt], bhi[j >> 1][(j & 1) * 2], bhi[j >> 1][(j & 1) * 2 + 1]);
#pragma unroll
        for (int mt = 0; mt < 2; mt++)
#pragma unroll
            for (int j = 0; j < 4; j++)
                mma16816(c[mt][j], ahi[mt], blo[j >> 1][(j & 1) * 2], blo[j >> 1][(j & 1) * 2 + 1]);
#pragma unroll
        for (int mt = 0; mt < 2; mt++)
#pragma unroll
            for (int j = 0; j < 4; j++)
                mma16816(c[mt][j], alo[mt], bhi[j >> 1][(j & 1) * 2], bhi[j >> 1][(j & 1) * 2 + 1]);
    }
}

// ---------------------------------------------------------------------------
// Prep kernels
// ---------------------------------------------------------------------------
__device__ __forceinline__ void split16(float v, __half* hi, __half* lo) {
    __half h = __float2half_rn(v);
    *hi = h;
    *lo = __float2half_rn(v - __half2float(h));
}

__global__ void prep_w(const float* __restrict__ W_ih, const float* __restrict__ W_hh,
                       const float* __restrict__ b_ih, const float* __restrict__ b_hh) {
    int idx = blockIdx.x * 256 + threadIdx.x;
    if (idx < NGATE * KTOT) {
        int p = idx / KTOT, k = idx - p * KTOT;
        int j = p >> 2, g = p & 3;
        int srow = g * NH + j;
        float v = (k < NIN) ? W_ih[(size_t)srow * NIN + k]
                            : W_hh[(size_t)srow * NH + (k - NIN)];
        split16(v, &g_Whi[idx], &g_Wlo[idx]);
    }
    if (idx < NGATE) {
        int j = idx >> 2, g = idx & 3;
        g_bias[idx] = b_ih[g * NH + j] + b_hh[g * NH + j];
    }
}

__global__ void prep_wcls(const float* __restrict__ W_cls) {
    int idx = blockIdx.x * 256 + threadIdx.x;
    if (idx < NOUT * NH) split16(W_cls[idx], &g_Wchi[idx], &g_Wclo[idx]);
}

__global__ void prep_x(const float* __restrict__ input, const float* __restrict__ dtv) {
    int idx = blockIdx.x * 256 + threadIdx.x;
    if (idx < TT * BB * NIN) {
        int k = idx & (NIN - 1);
        int tb = idx >> 7;
        float v = (k < NIN - 1) ? input[(size_t)tb * (NIN - 1) + k] : dtv[tb];
        split16(v, &g_Xhi[idx], &g_Xlo[idx]);
    }
}

__global__ void prep_zero() {
    int idx = blockIdx.x * 256 + threadIdx.x;
    if (idx < BB * NH) {
        g_C[idx] = 0.0f;
        g_Hhi[idx] = __float2half_rn(0.0f);
        g_Hlo[idx] = __float2half_rn(0.0f);
    }
}

// ---------------------------------------------------------------------------
// Step kernel: gates[64b x 64cols] = [x_t|h_{t-1}] @ Wg^T, then cell update.
// grid (32 n-tiles, 4 m-groups) x 128 threads.
// ---------------------------------------------------------------------------
__global__ void __launch_bounds__(128) step_kernel(int t) {
    extern __shared__ char dyn[];
    __shared__ float s_bias[64];

    const uint32_t sb = smem_u32(dyn);
    const int tid = threadIdx.x, L = tid & 31, wid = tid >> 5;
    const int nt = blockIdx.x, mg = blockIdx.y, mbase = mg * 64;

    if (tid < 64) s_bias[tid] = g_bias[nt * 64 + tid];

    const __half* whiP = g_Whi + (size_t)(nt * 64) * KTOT;
    const __half* wloP = g_Wlo + (size_t)(nt * 64) * KTOT;
    const size_t xrow = ((size_t)t * BB + mbase);

    // stage 0 prologue
    load_stage(sb, tid, g_Xhi + xrow * NIN, g_Xlo + xrow * NIN, NIN, whiP, wloP, KTOT);

    float c[2][4][4];
#pragma unroll
    for (int a = 0; a < 2; a++)
#pragma unroll
        for (int b = 0; b < 4; b++)
#pragma unroll
            for (int d = 0; d < 4; d++) c[a][b][d] = 0.f;

    const int mwb = (wid & 1) * 32, nwb = (wid >> 1) * 32;
    const uint32_t aoff = (uint32_t)((((L >> 3) & 1) * 8 + (L & 7)) * ROWB + (L >> 4) * 16);
    const uint32_t boff = (uint32_t)(((L >> 4) * 8 + (L & 7)) * ROWB + ((L >> 3) & 1) * 16);

#pragma unroll 1
    for (int s = 0; s < SK_CHUNKS; s++) {
        if (s + 1 < SK_CHUNKS) {
            int sn = s + 1;
            const __half *ahi, *alo;
            int astr;
            if (sn < 2) { ahi = g_Xhi + xrow * NIN + sn * 64; alo = g_Xlo + xrow * NIN + sn * 64; astr = NIN; }
            else        { ahi = g_Hhi + xrow * NH + (sn - 2) * 64; alo = g_Hlo + xrow * NH + (sn - 2) * 64; astr = NH; }
            load_stage(sb + (sn & 1) * STAGEB, tid, ahi, alo, astr, whiP + sn * 64, wloP + sn * 64, KTOT);
            asm volatile("cp.async.wait_group 1;" ::: "memory");
        } else {
            asm volatile("cp.async.wait_group 0;" ::: "memory");
        }
        __syncthreads();
        compute_chunk(sb + (s & 1) * STAGEB, mwb, nwb, aoff, boff, c);
        __syncthreads();
    }

    // --- gates -> smem (reuse buffer 0), stride 272 B per row ---
#pragma unroll
    for (int mt = 0; mt < 2; mt++)
#pragma unroll
        for (int j = 0; j < 4; j++) {
            int row = mwb + mt * 16 + (L >> 2);
            int col = nwb + j * 8 + 2 * (L & 3);
            *(float2*)(dyn + row * 272 + col * 4) = make_float2(c[mt][j][0], c[mt][j][1]);
            *(float2*)(dyn + (row + 8) * 272 + col * 4) = make_float2(c[mt][j][2], c[mt][j][3]);
        }
    __syncthreads();

    // --- LSTM cell update: thread -> (row, 8 units) ---
    {
        const int row = tid >> 1;
        const int ub = (tid & 1) * 8;
        const int brow = mbase + row;
        float* cp = g_C + (size_t)brow * NH + nt * 16 + ub;
        __half* hh = g_Hhi + ((size_t)(t + 1) * BB + brow) * NH + nt * 16 + ub;
        __half* hl = g_Hlo + ((size_t)(t + 1) * BB + brow) * NH + nt * 16 + ub;

        float4 co01 = ((const float4*)cp)[0];
        float4 co23 = ((const float4*)cp)[1];
        float cold[8] = {co01.x, co01.y, co01.z, co01.w, co23.x, co23.y, co23.z, co23.w};
        float cn[8];
        uint16_t hhi[8], hlo[8];
#pragma unroll
        for (int j = 0; j < 8; j++) {
            float4 gv = *(const float4*)(dyn + row * 272 + (ub + j) * 16);
            float4 bb = *(const float4*)((const char*)s_bias + (ub + j) * 16);
            float iv = fsigmoid(gv.x + bb.x);
            float fv = fsigmoid(gv.y + bb.y);
            float gg = ftanh(gv.z + bb.z);
            float ov = fsigmoid(gv.w + bb.w);
            float cv = fv * cold[j] + iv * gg;
            cn[j] = cv;
            float hv = ov * ftanh(cv);
            __half h = __float2half_rn(hv);
            hhi[j] = __half_as_ushort(h);
            hlo[j] = __half_as_ushort(__float2half_rn(hv - __half2float(h)));
        }
        ((float4*)cp)[0] = make_float4(cn[0], cn[1], cn[2], cn[3]);
        ((float4*)cp)[1] = make_float4(cn[4], cn[5], cn[6], cn[7]);
        uint4 ph, pl;
        ph.x = (uint32_t)hhi[0] | ((uint32_t)hhi[1] << 16);
        ph.y = (uint32_t)hhi[2] | ((uint32_t)hhi[3] << 16);
        ph.z = (uint32_t)hhi[4] | ((uint32_t)hhi[5] << 16);
        ph.w = (uint32_t)hhi[6] | ((uint32_t)hhi[7] << 16);
        pl.x = (uint32_t)hlo[0] | ((uint32_t)hlo[1] << 16);
        pl.y = (uint32_t)hlo[2] | ((uint32_t)hlo[3] << 16);
        pl.z = (uint32_t)hlo[4] | ((uint32_t)hlo[5] << 16);
        pl.w = (uint32_t)hlo[6] | ((uint32_t)hlo[7] << 16);
        *(uint4*)hh = ph;
        *(uint4*)hl = pl;
    }
}

// ---------------------------------------------------------------------------
// Classifier: out[131072,64] = hs @ W_cls^T + b_cls. grid 2048 x 128 thr.
// ---------------------------------------------------------------------------
__global__ void __launch_bounds__(128) cls_kernel(const float* __restrict__ b_cls,
                                                  float* __restrict__ out) {
    extern __shared__ char dyn[];
    __shared__ float s_bias[64];

    const uint32_t sb = smem_u32(dyn);
    const int tid = threadIdx.x, L = tid & 31, wid = tid >> 5;
    const size_t mb = (size_t)blockIdx.x * 64;

    if (tid < 64) s_bias[tid] = b_cls[tid];

    const __half* ahi0 = g_Hhi + (BB + mb) * NH;
    const __half* alo0 = g_Hlo + (BB + mb) * NH;

    load_stage(sb, tid, ahi0, alo0, NH, g_Wchi, g_Wclo, NH);

    float c[2][4][4];
#pragma unroll
    for (int a = 0; a < 2; a++)
#pragma unroll
        for (int b = 0; b < 4; b++)
#pragma unroll
            for (int d = 0; d < 4; d++) c[a][b][d] = 0.f;

    const int mwb = (wid & 1) * 32, nwb = (wid >> 1) * 32;
    const uint32_t aoff = (uint32_t)((((L >> 3) & 1) * 8 + (L & 7)) * ROWB + (L >> 4) * 16);
    const uint32_t boff = (uint32_t)(((L >> 4) * 8 + (L & 7)) * ROWB + ((L >> 3) & 1) * 16);

#pragma unroll 1
    for (int s = 0; s < CLS_CHUNKS; s++) {
        if (s + 1 < CLS_CHUNKS) {
            int sn = s + 1;
            load_stage(sb + (sn & 1) * STAGEB, tid, ahi0 + sn * 64, alo0 + sn * 64, NH,
                       g_Wchi + sn * 64, g_Wclo + sn * 64, NH);
            asm volatile("cp.async.wait_group 1;" ::: "memory");
        } else {
            asm volatile("cp.async.wait_group 0;" ::: "memory");
        }
        __syncthreads();
        compute_chunk(sb + (s & 1) * STAGEB, mwb, nwb, aoff, boff, c);
        __syncthreads();
    }

#pragma unroll
    for (int mt = 0; mt < 2; mt++)
#pragma unroll
        for (int j = 0; j < 4; j++) {
            int row = mwb + mt * 16 + (L >> 2);
            int col = nwb + j * 8 + 2 * (L & 3);
            float2 bb = *(const float2*)((const char*)s_bias + col * 4);
            float* op = out + (mb + row) * NOUT + col;
            *(float2*)op = make_float2(c[mt][j][0] + bb.x, c[mt][j][1] + bb.y);
            *(float2*)(op + 8 * NOUT) = make_float2(c[mt][j][2] + bb.x, c[mt][j][3] + bb.y);
        }
}

// ---------------------------------------------------------------------------
// Launch
// ---------------------------------------------------------------------------
extern "C" void kernel_launch(void* const* d_in, const int* in_sizes, int n_in,
                              void* d_out, int out_size) {
    const float* input = (const float*)d_in[0];
    const float* dtv   = (const float*)d_in[1];
    const float* W_ih  = (const float*)d_in[2];
    const float* W_hh  = (const float*)d_in[3];
    const float* b_ih  = (const float*)d_in[4];
    const float* b_hh  = (const float*)d_in[5];
    const float* W_cls = (const float*)d_in[6];
    const float* b_cls = (const float*)d_in[7];
    float* out = (float*)d_out;

    cudaFuncSetAttribute(step_kernel, cudaFuncAttributeMaxDynamicSharedMemorySize, DYN_SMEM);
    cudaFuncSetAttribute(cls_kernel, cudaFuncAttributeMaxDynamicSharedMemorySize, DYN_SMEM);

    prep_w<<<(NGATE * KTOT + 255) / 256, 256>>>(W_ih, W_hh, b_ih, b_hh);
    prep_wcls<<<(NOUT * NH + 255) / 256, 256>>>(W_cls);
    prep_x<<<(TT * BB * NIN + 255) / 256, 256>>>(input, dtv);
    prep_zero<<<(BB * NH + 255) / 256, 256>>>();

    for (int t = 0; t < TT; t++)
        step_kernel<<<dim3(32, 4), 128, DYN_SMEM>>>(t);

    cls_kernel<<<2048, 128, DYN_SMEM>>>(b_cls, out);
}

// round 5
// speedup vs baseline: 1.1910x; 1.1910x over previous
#include <cuda_runtime.h>
#include <cuda_fp16.h>
#include <cstdint>
#include <cstddef>

// ---------------------------------------------------------------------------
// Problem constants
// ---------------------------------------------------------------------------
#define TT    512
#define BB    256
#define NIN   128      // NINP (127 input + 1 dt)
#define NH    512      // NHID
#define NGATE 2048     // 4*NHID
#define KTOT  640      // NIN + NH
#define NOUT  64

// Tiling: CTA = 64 rows x 64 gate-cols, K chunks of 64, fp16 hi/lo split.
#define ROWB   144             // smem row stride (64 fp16 = 128B + 16B pad)
#define PLANE  (64 * ROWB)     // 9216 B per 64x64 fp16 plane
#define ASTAGE (2 * PLANE)     // A stage = hi+lo planes = 18432 B
#define SK_CHUNKS 10           // 640/64
#define CLS_CHUNKS 8           // 512/64
#define WREGION (SK_CHUNKS * 2 * PLANE)          // 184320 B resident W
#define PERS_SMEM (2 * ASTAGE + WREGION)         // 221184 B
#define STAGEB (4 * PLANE)                       // cls: A(2)+W(2) planes
#define CLS_SMEM (2 * STAGEB)                    // 73728 B

// ---------------------------------------------------------------------------
// Device scratch
// ---------------------------------------------------------------------------
__device__ __half g_Xhi[(size_t)TT * BB * NIN];
__device__ __half g_Xlo[(size_t)TT * BB * NIN];
__device__ __half g_Whi[(size_t)NGATE * KTOT];   // permuted: row 4j+g
__device__ __half g_Wlo[(size_t)NGATE * KTOT];
__device__ __half g_Wchi[(size_t)NOUT * NH];
__device__ __half g_Wclo[(size_t)NOUT * NH];
__device__ float  g_bias[NGATE];
__device__ __half g_Hhi[(size_t)(TT + 1) * BB * NH];  // slot s = h_{s-1}
__device__ __half g_Hlo[(size_t)(TT + 1) * BB * NH];
__device__ unsigned g_bar;                       // grid barrier counter

// ---------------------------------------------------------------------------
// Helpers
// ---------------------------------------------------------------------------
__device__ __forceinline__ uint32_t smem_u32(const void* p) {
    uint32_t a;
    asm("{ .reg .u64 t; cvta.to.shared.u64 t, %1; cvt.u32.u64 %0, t; }" : "=r"(a) : "l"(p));
    return a;
}

__device__ __forceinline__ void ldsm4(uint32_t addr, uint32_t r[4]) {
    asm volatile("ldmatrix.sync.aligned.m8n8.x4.shared.b16 {%0,%1,%2,%3}, [%4];"
                 : "=r"(r[0]), "=r"(r[1]), "=r"(r[2]), "=r"(r[3]) : "r"(addr));
}

__device__ __forceinline__ void mma16816(float c[4], const uint32_t a[4],
                                         uint32_t b0, uint32_t b1) {
    asm volatile("mma.sync.aligned.m16n8k16.row.col.f32.f16.f16.f32 "
                 "{%0,%1,%2,%3}, {%4,%5,%6,%7}, {%8,%9}, {%0,%1,%2,%3};"
                 : "+f"(c[0]), "+f"(c[1]), "+f"(c[2]), "+f"(c[3])
                 : "r"(a[0]), "r"(a[1]), "r"(a[2]), "r"(a[3]), "r"(b0), "r"(b1));
}

__device__ __forceinline__ void cpa16(uint32_t dst, const void* src) {
    asm volatile("cp.async.cg.shared.global [%0], [%1], 16;" :: "r"(dst), "l"(src));
}
#define CP_COMMIT() asm volatile("cp.async.commit_group;" ::: "memory")

__device__ __forceinline__ float fsigmoid(float x) {
    x = fminf(fmaxf(x, -30.f), 30.f);
    return 1.0f / (1.0f + __expf(-x));
}
__device__ __forceinline__ float ftanh(float x) {
    x = fminf(fmaxf(x, -15.f), 15.f);
    float e = __expf(-2.0f * x);
    return (1.0f - e) / (1.0f + e);
}

// Load one 64x64 hi+lo A stage via cp.async (commits one group).
__device__ __forceinline__ void load_A(uint32_t dst, int tid,
                                       const __half* hi, const __half* lo, int astr) {
#pragma unroll
    for (int i = 0; i < 8; i++) {
        int idx = tid + 128 * i;               // 0..1023
        int plane = idx >> 9, rem = idx & 511, r = rem >> 3, ch = rem & 7;
        const __half* src = (plane ? lo : hi) + (size_t)r * astr + ch * 8;
        cpa16(dst + plane * PLANE + r * ROWB + ch * 16, src);
    }
    CP_COMMIT();
}

// One K=64 chunk: A from abase (hi at +0, lo at +PLANE), B from wbase likewise.
__device__ __forceinline__ void compute_chunk(uint32_t abase, uint32_t wbase,
                                              int mwb, int nwb,
                                              uint32_t aoff, uint32_t boff,
                                              float c[2][4][4]) {
#pragma unroll
    for (int kk = 0; kk < 4; kk++) {
        uint32_t ahi[2][4], alo[2][4], bhi[2][4], blo[2][4];
#pragma unroll
        for (int mt = 0; mt < 2; mt++) {
            uint32_t base = abase + (uint32_t)(mwb + mt * 16) * ROWB + kk * 32 + aoff;
            ldsm4(base, ahi[mt]);
            ldsm4(base + PLANE, alo[mt]);
        }
#pragma unroll
        for (int q = 0; q < 2; q++) {
            uint32_t base = wbase + (uint32_t)(nwb + q * 16) * ROWB + kk * 32 + boff;
            ldsm4(base, bhi[q]);
            ldsm4(base + PLANE, blo[q]);
        }
        // three passes: hi*hi + hi*lo + lo*hi (8-instruction dependency spacing)
#pragma unroll
        for (int mt = 0; mt < 2; mt++)
#pragma unroll
            for (int j = 0; j < 4; j++)
                mma16816(c[mt][j], ahi[mt], bhi[j >> 1][(j & 1) * 2], bhi[j >> 1][(j & 1) * 2 + 1]);
#pragma unroll
        for (int mt = 0; mt < 2; mt++)
#pragma unroll
            for (int j = 0; j < 4; j++)
                mma16816(c[mt][j], ahi[mt], blo[j >> 1][(j & 1) * 2], blo[j >> 1][(j & 1) * 2 + 1]);
#pragma unroll
        for (int mt = 0; mt < 2; mt++)
#pragma unroll
            for (int j = 0; j < 4; j++)
                mma16816(c[mt][j], alo[mt], bhi[j >> 1][(j & 1) * 2], bhi[j >> 1][(j & 1) * 2 + 1]);
    }
}

// ---------------------------------------------------------------------------
// Prep kernels
// ---------------------------------------------------------------------------
__device__ __forceinline__ void split16(float v, __half* hi, __half* lo) {
    __half h = __float2half_rn(v);
    *hi = h;
    *lo = __float2half_rn(v - __half2float(h));
}

__global__ void prep_w(const float* __restrict__ W_ih, const float* __restrict__ W_hh,
                       const float* __restrict__ b_ih, const float* __restrict__ b_hh) {
    int idx = blockIdx.x * 256 + threadIdx.x;
    if (idx < NGATE * KTOT) {
        int p = idx / KTOT, k = idx - p * KTOT;
        int j = p >> 2, g = p & 3;
        int srow = g * NH + j;
        float v = (k < NIN) ? W_ih[(size_t)srow * NIN + k]
                            : W_hh[(size_t)srow * NH + (k - NIN)];
        split16(v, &g_Whi[idx], &g_Wlo[idx]);
    }
    if (idx < NGATE) {
        int j = idx >> 2, g = idx & 3;
        g_bias[idx] = b_ih[g * NH + j] + b_hh[g * NH + j];
    }
}

__global__ void prep_wcls(const float* __restrict__ W_cls) {
    int idx = blockIdx.x * 256 + threadIdx.x;
    if (idx < NOUT * NH) split16(W_cls[idx], &g_Wchi[idx], &g_Wclo[idx]);
}

__global__ void prep_x(const float* __restrict__ input, const float* __restrict__ dtv) {
    int idx = blockIdx.x * 256 + threadIdx.x;
    if (idx < TT * BB * NIN) {
        int k = idx & (NIN - 1);
        int tb = idx >> 7;
        float v = (k < NIN - 1) ? input[(size_t)tb * (NIN - 1) + k] : dtv[tb];
        split16(v, &g_Xhi[idx], &g_Xlo[idx]);
    }
}

__global__ void prep_zero() {
    int idx = blockIdx.x * 256 + threadIdx.x;
    if (idx == 0) g_bar = 0;
    if (idx < BB * NH) {
        g_Hhi[idx] = __float2half_rn(0.0f);   // h_{-1}
        g_Hlo[idx] = __float2half_rn(0.0f);
    }
}

// ---------------------------------------------------------------------------
// Persistent kernel: all 512 LSTM steps in one launch.
// grid (32 n-tiles, 4 m-groups) = 128 CTAs (one wave, 1 CTA/SM), 128 threads.
// W resident in smem; c in registers; grid barrier between steps; x chunks of
// step t+1 prefetched across the barrier. Spin has a trap-on-timeout guard so
// a genuine deadlock aborts loudly instead of killing the container.
// ---------------------------------------------------------------------------
__global__ void __launch_bounds__(128) persistent_step() {
    extern __shared__ char dyn[];
    __shared__ float s_bias[64];

    const uint32_t sb = smem_u32(dyn);
    const uint32_t wb = sb + 2 * ASTAGE;            // resident W region
    const int tid = threadIdx.x, L = tid & 31, wid = tid >> 5;
    const int nt = blockIdx.x, mg = blockIdx.y, mbase = mg * 64;

    if (tid < 64) s_bias[tid] = g_bias[nt * 64 + tid];

    // --- load resident W: 10 chunks x (hi,lo) planes, one cp.async group ---
#pragma unroll 4
    for (int i = 0; i < 80; i++) {
        int idx = tid + 128 * i;                    // 0..10239
        int pl = idx >> 9;                          // plane 0..19
        int rem = idx & 511, r = rem >> 3, ch = rem & 7;
        int s = pl >> 1, hl = pl & 1;
        const __half* src = (hl ? g_Wlo : g_Whi)
                          + (size_t)(nt * 64 + r) * KTOT + s * 64 + ch * 8;
        cpa16(wb + (uint32_t)pl * PLANE + r * ROWB + ch * 16, src);
    }
    CP_COMMIT();

    // --- prefetch x chunks 0,1 of t=0 ---
    {
        const size_t xrow = (size_t)0 * BB + mbase;
        load_A(sb,          tid, g_Xhi + xrow * NIN,      g_Xlo + xrow * NIN,      NIN);
        load_A(sb + ASTAGE, tid, g_Xhi + xrow * NIN + 64, g_Xlo + xrow * NIN + 64, NIN);
    }

    const int mwb = (wid & 1) * 32, nwb = (wid >> 1) * 32;
    const uint32_t aoff = (uint32_t)((((L >> 3) & 1) * 8 + (L & 7)) * ROWB + (L >> 4) * 16);
    const uint32_t boff = (uint32_t)(((L >> 4) * 8 + (L & 7)) * ROWB + ((L >> 3) & 1) * 16);

    // persistent cell state: thread -> (row = tid>>1, units nt*16 + (tid&1)*8 ..+7)
    float creg[8];
#pragma unroll
    for (int j = 0; j < 8; j++) creg[j] = 0.f;

    unsigned* barp = &g_bar;

#pragma unroll 1
    for (int t = 0; t < TT; t++) {
        const size_t hrow = ((size_t)t * BB + mbase);

        float c[2][4][4];
#pragma unroll
        for (int a = 0; a < 2; a++)
#pragma unroll
            for (int b = 0; b < 4; b++)
#pragma unroll
                for (int d = 0; d < 4; d++) c[a][b][d] = 0.f;

#pragma unroll 1
        for (int s = 0; s < SK_CHUNKS; s++) {
            if (s == SK_CHUNKS - 1) asm volatile("cp.async.wait_group 0;" ::: "memory");
            else                    asm volatile("cp.async.wait_group 1;" ::: "memory");
            __syncthreads();
            compute_chunk(sb + (s & 1) * ASTAGE, wb + (uint32_t)s * 2 * PLANE,
                          mwb, nwb, aoff, boff, c);
            __syncthreads();
            if (s + 2 < SK_CHUNKS) {   // chunk s+2 is h_{t-1} data (k offset s*64)
                load_A(sb + (s & 1) * ASTAGE, tid,
                       g_Hhi + hrow * NH + s * 64, g_Hlo + hrow * NH + s * 64, NH);
            }
        }

        // --- gates -> smem (buf0 region), stride 272 B/row ---
#pragma unroll
        for (int mt = 0; mt < 2; mt++)
#pragma unroll
            for (int j = 0; j < 4; j++) {
                int row = mwb + mt * 16 + (L >> 2);
                int col = nwb + j * 8 + 2 * (L & 3);
                *(float2*)(dyn + row * 272 + col * 4) = make_float2(c[mt][j][0], c[mt][j][1]);
                *(float2*)(dyn + (row + 8) * 272 + col * 4) = make_float2(c[mt][j][2], c[mt][j][3]);
            }
        __syncthreads();

        // --- cell update (c in registers), h -> global hi/lo ---
        {
            const int row = tid >> 1;
            const int ub = (tid & 1) * 8;
            const int brow = mbase + row;
            __half* hh = g_Hhi + ((size_t)(t + 1) * BB + brow) * NH + nt * 16 + ub;
            __half* hl = g_Hlo + ((size_t)(t + 1) * BB + brow) * NH + nt * 16 + ub;

            uint16_t hhi[8], hlo[8];
#pragma unroll
            for (int j = 0; j < 8; j++) {
                float4 gv = *(const float4*)(dyn + row * 272 + (ub + j) * 16);
                float4 bb2 = *(const float4*)((const char*)s_bias + (ub + j) * 16);
                float iv = fsigmoid(gv.x + bb2.x);
                float fv = fsigmoid(gv.y + bb2.y);
                float gg = ftanh(gv.z + bb2.z);
                float ov = fsigmoid(gv.w + bb2.w);
                float cv = fv * creg[j] + iv * gg;
                creg[j] = cv;
                float hv = ov * ftanh(cv);
                __half h = __float2half_rn(hv);
                hhi[j] = __half_as_ushort(h);
                hlo[j] = __half_as_ushort(__float2half_rn(hv - __half2float(h)));
            }
            uint4 ph, pl;
            ph.x = (uint32_t)hhi[0] | ((uint32_t)hhi[1] << 16);
            ph.y = (uint32_t)hhi[2] | ((uint32_t)hhi[3] << 16);
            ph.z = (uint32_t)hhi[4] | ((uint32_t)hhi[5] << 16);
            ph.w = (uint32_t)hhi[6] | ((uint32_t)hhi[7] << 16);
            pl.x = (uint32_t)hlo[0] | ((uint32_t)hlo[1] << 16);
            pl.y = (uint32_t)hlo[2] | ((uint32_t)hlo[3] << 16);
            pl.z = (uint32_t)hlo[4] | ((uint32_t)hlo[5] << 16);
            pl.w = (uint32_t)hlo[6] | ((uint32_t)hlo[7] << 16);
            *(uint4*)hh = ph;
            *(uint4*)hl = pl;
        }
        __syncthreads();   // gates fully consumed before prefetch overwrites buf0

        if (t + 1 < TT) {
            // prefetch next step's x chunks (independent of h) — overlaps barrier
            const size_t xrow = ((size_t)(t + 1) * BB + mbase);
            load_A(sb,          tid, g_Xhi + xrow * NIN,      g_Xlo + xrow * NIN,      NIN);
            load_A(sb + ASTAGE, tid, g_Xhi + xrow * NIN + 64, g_Xlo + xrow * NIN + 64, NIN);

            // grid barrier: h_{t} (slot t+1) visible to all CTAs
            __threadfence();
            __syncthreads();
            if (tid == 0) {
                atomicAdd(barp, 1u);
                const unsigned target = 128u * (unsigned)(t + 1);
                unsigned v;
                unsigned long long guard = 0;
                do {
                    asm volatile("ld.acquire.gpu.global.u32 %0, [%1];" : "=r"(v) : "l"(barp));
                    if (v >= target) break;
                    asm volatile("nanosleep.u32 64;");
                    if (++guard > 200000000ULL) __trap();   // loud abort on deadlock
                } while (true);
            }
            __syncthreads();
        }
    }
}

// ---------------------------------------------------------------------------
// Classifier: out[131072,64] = hs @ W_cls^T + b_cls. grid 2048 x 128 thr.
// ---------------------------------------------------------------------------
__global__ void __launch_bounds__(128) cls_kernel(const float* __restrict__ b_cls,
                                                  float* __restrict__ out) {
    extern __shared__ char dyn[];
    __shared__ float s_bias[64];

    const uint32_t sb = smem_u32(dyn);
    const int tid = threadIdx.x, L = tid & 31, wid = tid >> 5;
    const size_t mb = (size_t)blockIdx.x * 64;

    if (tid < 64) s_bias[tid] = b_cls[tid];

    const __half* ahi0 = g_Hhi + (BB + mb) * NH;
    const __half* alo0 = g_Hlo + (BB + mb) * NH;

    // stage s: A at base + (s&1)*STAGEB, W planes at +2*PLANE
    load_A(sb, tid, ahi0, alo0, NH);
    load_A(sb + 2 * PLANE, tid, g_Wchi, g_Wclo, NH);

    float c[2][4][4];
#pragma unroll
    for (int a = 0; a < 2; a++)
#pragma unroll
        for (int b = 0; b < 4; b++)
#pragma unroll
            for (int d = 0; d < 4; d++) c[a][b][d] = 0.f;

    const int mwb = (wid & 1) * 32, nwb = (wid >> 1) * 32;
    const uint32_t aoff = (uint32_t)((((L >> 3) & 1) * 8 + (L & 7)) * ROWB + (L >> 4) * 16);
    const uint32_t boff = (uint32_t)(((L >> 4) * 8 + (L & 7)) * ROWB + ((L >> 3) & 1) * 16);

#pragma unroll 1
    for (int s = 0; s < CLS_CHUNKS; s++) {
        if (s + 1 < CLS_CHUNKS) {
            int sn = s + 1;
            uint32_t nb = sb + (sn & 1) * STAGEB;
            load_A(nb, tid, ahi0 + sn * 64, alo0 + sn * 64, NH);
            load_A(nb + 2 * PLANE, tid, g_Wchi + sn * 64, g_Wclo + sn * 64, NH);
            asm volatile("cp.async.wait_group 2;" ::: "memory");
        } else {
            asm volatile("cp.async.wait_group 0;" ::: "memory");
        }
        __syncthreads();
        uint32_t base = sb + (s & 1) * STAGEB;
        compute_chunk(base, base + 2 * PLANE, mwb, nwb, aoff, boff, c);
        __syncthreads();
    }

#pragma unroll
    for (int mt = 0; mt < 2; mt++)
#pragma unroll
        for (int j = 0; j < 4; j++) {
            int row = mwb + mt * 16 + (L >> 2);
            int col = nwb + j * 8 + 2 * (L & 3);
            float2 bb = *(const float2*)((const char*)s_bias + col * 4);
            float* op = out + (mb + row) * NOUT + col;
            *(float2*)op = make_float2(c[mt][j][0] + bb.x, c[mt][j][1] + bb.y);
            *(float2*)(op + 8 * NOUT) = make_float2(c[mt][j][2] + bb.x, c[mt][j][3] + bb.y);
        }
}

// ---------------------------------------------------------------------------
// Launch
// ---------------------------------------------------------------------------
extern "C" void kernel_launch(void* const* d_in, const int* in_sizes, int n_in,
                              void* d_out, int out_size) {
    const float* input = (const float*)d_in[0];
    const float* dtv   = (const float*)d_in[1];
    const float* W_ih  = (const float*)d_in[2];
    const float* W_hh  = (const float*)d_in[3];
    const float* b_ih  = (const float*)d_in[4];
    const float* b_hh  = (const float*)d_in[5];
    const float* W_cls = (const float*)d_in[6];
    const float* b_cls = (const float*)d_in[7];
    float* out = (float*)d_out;

    cudaFuncSetAttribute(persistent_step, cudaFuncAttributeMaxDynamicSharedMemorySize, PERS_SMEM);
    cudaFuncSetAttribute(cls_kernel, cudaFuncAttributeMaxDynamicSharedMemorySize, CLS_SMEM);

    prep_w<<<(NGATE * KTOT + 255) / 256, 256>>>(W_ih, W_hh, b_ih, b_hh);
    prep_wcls<<<(NOUT * NH + 255) / 256, 256>>>(W_cls);
    prep_x<<<(TT * BB * NIN + 255) / 256, 256>>>(input, dtv);
    prep_zero<<<(BB * NH + 255) / 256, 256>>>();

    persistent_step<<<dim3(32, 4), 128, PERS_SMEM>>>();
    cls_kernel<<<2048, 128, CLS_SMEM>>>(b_cls, out);
}

// round 7
// speedup vs baseline: 1.4194x; 1.1918x over previous
#include <cuda_runtime.h>
#include <cuda_fp16.h>
#include <cstdint>
#include <cstddef>

// ---------------------------------------------------------------------------
// Problem constants
// ---------------------------------------------------------------------------
#define TT    512
#define BB    256
#define NIN   128      // NINP (127 input + 1 dt)
#define NH    512      // NHID
#define NGATE 2048     // 4*NHID
#define KTOT  640      // NIN + NH
#define NOUT  64

// Tiling: CTA = 64 rows x 64 gate-cols, K chunks of 64.
// A (x,h) plain fp16; W split hi+lo (resident); 2-pass MMA.
#define ROWB   144             // smem row stride (64 fp16 = 128B + 16B pad)
#define PLANE  (64 * ROWB)     // 9216 B per 64x64 fp16 plane
#define SK_CHUNKS 10           // 640/64
#define CLS_CHUNKS 8           // 512/64
#define NABUF  4               // A pipeline depth
#define WREGION (SK_CHUNKS * 2 * PLANE)          // 184320 B resident W
#define PERS_SMEM (NABUF * PLANE + WREGION)      // 221184 B
#define CLS_STAGE (3 * PLANE)                    // A + Whi + Wlo
#define CLS_SMEM (2 * CLS_STAGE)                 // 55296 B

// ---------------------------------------------------------------------------
// Device scratch
// ---------------------------------------------------------------------------
__device__ __half g_Xh[(size_t)TT * BB * NIN];    // fp16 [x|dt]
__device__ __half g_Whi[(size_t)NGATE * KTOT];    // permuted: row 4j+g
__device__ __half g_Wlo[(size_t)NGATE * KTOT];
__device__ __half g_Wchi[(size_t)NOUT * NH];
__device__ __half g_Wclo[(size_t)NOUT * NH];
__device__ float  g_bias[NGATE];
__device__ __half g_Hh[(size_t)(TT + 1) * BB * NH];  // slot s = h_{s-1}
__device__ unsigned g_bar;                        // grid barrier counter

// ---------------------------------------------------------------------------
// Helpers
// ---------------------------------------------------------------------------
__device__ __forceinline__ uint32_t smem_u32(const void* p) {
    uint32_t a;
    asm("{ .reg .u64 t; cvta.to.shared.u64 t, %1; cvt.u32.u64 %0, t; }" : "=r"(a) : "l"(p));
    return a;
}

__device__ __forceinline__ void ldsm4(uint32_t addr, uint32_t r[4]) {
    asm volatile("ldmatrix.sync.aligned.m8n8.x4.shared.b16 {%0,%1,%2,%3}, [%4];"
                 : "=r"(r[0]), "=r"(r[1]), "=r"(r[2]), "=r"(r[3]) : "r"(addr));
}

__device__ __forceinline__ void mma16816(float c[4], const uint32_t a[4],
                                         uint32_t b0, uint32_t b1) {
    asm volatile("mma.sync.aligned.m16n8k16.row.col.f32.f16.f16.f32 "
                 "{%0,%1,%2,%3}, {%4,%5,%6,%7}, {%8,%9}, {%0,%1,%2,%3};"
                 : "+f"(c[0]), "+f"(c[1]), "+f"(c[2]), "+f"(c[3])
                 : "r"(a[0]), "r"(a[1]), "r"(a[2]), "r"(a[3]), "r"(b0), "r"(b1));
}

__device__ __forceinline__ void cpa16(uint32_t dst, const void* src) {
    asm volatile("cp.async.cg.shared.global [%0], [%1], 16;" :: "r"(dst), "l"(src));
}
#define CP_COMMIT() asm volatile("cp.async.commit_group;" ::: "memory")

__device__ __forceinline__ float fsigmoid(float x) {
    x = fminf(fmaxf(x, -30.f), 30.f);
    return 1.0f / (1.0f + __expf(-x));
}
__device__ __forceinline__ float ftanh(float x) {
    x = fminf(fmaxf(x, -15.f), 15.f);
    float e = __expf(-2.0f * x);
    return (1.0f - e) / (1.0f + e);
}

// Load one 64x64 fp16 plane via cp.async (one commit group).
__device__ __forceinline__ void load_A(uint32_t dst, int tid,
                                       const __half* src0, int astr) {
#pragma unroll
    for (int i = 0; i < 4; i++) {
        int idx = tid + 128 * i;               // 0..511
        int r = idx >> 3, ch = idx & 7;
        cpa16(dst + r * ROWB + ch * 16, src0 + (size_t)r * astr + ch * 8);
    }
    CP_COMMIT();
}

// One K=64 chunk, 2-pass: c += A*Whi + A*Wlo. A plane at abase; W hi plane at
// wbase, lo plane at wbase+PLANE.
__device__ __forceinline__ void compute_chunk(uint32_t abase, uint32_t wbase,
                                              int mwb, int nwb,
                                              uint32_t aoff, uint32_t boff,
                                              float c[2][4][4]) {
#pragma unroll
    for (int kk = 0; kk < 4; kk++) {
        uint32_t a[2][4], bhi[2][4], blo[2][4];
#pragma unroll
        for (int mt = 0; mt < 2; mt++)
            ldsm4(abase + (uint32_t)(mwb + mt * 16) * ROWB + kk * 32 + aoff, a[mt]);
#pragma unroll
        for (int q = 0; q < 2; q++) {
            uint32_t base = wbase + (uint32_t)(nwb + q * 16) * ROWB + kk * 32 + boff;
            ldsm4(base, bhi[q]);
            ldsm4(base + PLANE, blo[q]);
        }
#pragma unroll
        for (int mt = 0; mt < 2; mt++)
#pragma unroll
            for (int j = 0; j < 4; j++)
                mma16816(c[mt][j], a[mt], bhi[j >> 1][(j & 1) * 2], bhi[j >> 1][(j & 1) * 2 + 1]);
#pragma unroll
        for (int mt = 0; mt < 2; mt++)
#pragma unroll
            for (int j = 0; j < 4; j++)
                mma16816(c[mt][j], a[mt], blo[j >> 1][(j & 1) * 2], blo[j >> 1][(j & 1) * 2 + 1]);
    }
}

// ---------------------------------------------------------------------------
// Prep kernels
// ---------------------------------------------------------------------------
__device__ __forceinline__ void split16(float v, __half* hi, __half* lo) {
    __half h = __float2half_rn(v);
    *hi = h;
    *lo = __float2half_rn(v - __half2float(h));
}

__global__ void prep_w(const float* __restrict__ W_ih, const float* __restrict__ W_hh,
                       const float* __restrict__ b_ih, const float* __restrict__ b_hh) {
    int idx = blockIdx.x * 256 + threadIdx.x;
    if (idx < NGATE * KTOT) {
        int p = idx / KTOT, k = idx - p * KTOT;
        int j = p >> 2, g = p & 3;
        int srow = g * NH + j;
        float v = (k < NIN) ? W_ih[(size_t)srow * NIN + k]
                            : W_hh[(size_t)srow * NH + (k - NIN)];
        split16(v, &g_Whi[idx], &g_Wlo[idx]);
    }
    if (idx < NGATE) {
        int j = idx >> 2, g = idx & 3;
        g_bias[idx] = b_ih[g * NH + j] + b_hh[g * NH + j];
    }
}

__global__ void prep_wcls(const float* __restrict__ W_cls) {
    int idx = blockIdx.x * 256 + threadIdx.x;
    if (idx < NOUT * NH) split16(W_cls[idx], &g_Wchi[idx], &g_Wclo[idx]);
}

__global__ void prep_x(const float* __restrict__ input, const float* __restrict__ dtv) {
    int idx = blockIdx.x * 256 + threadIdx.x;
    if (idx < TT * BB * NIN) {
        int k = idx & (NIN - 1);
        int tb = idx >> 7;
        float v = (k < NIN - 1) ? input[(size_t)tb * (NIN - 1) + k] : dtv[tb];
        g_Xh[idx] = __float2half_rn(v);
    }
}

__global__ void prep_zero() {
    int idx = blockIdx.x * 256 + threadIdx.x;
    if (idx == 0) g_bar = 0;
    if (idx < BB * NH) g_Hh[idx] = __float2half_rn(0.0f);   // h_{-1}
}

// ---------------------------------------------------------------------------
// Persistent kernel: all 512 LSTM steps in one launch.
// grid (32 n-tiles, 4 m-groups) = 128 CTAs (1/SM), 128 threads.
// W (hi+lo) resident in smem; A pipeline depth 4; c in registers; grid barrier
// between steps with trap-on-timeout; x chunks of t+1 prefetched across it.
// ---------------------------------------------------------------------------
__global__ void __launch_bounds__(128) persistent_step() {
    extern __shared__ char dyn[];
    __shared__ float s_bias[64];

    const uint32_t sb = smem_u32(dyn);                 // 4 A buffers
    const uint32_t wb = sb + NABUF * PLANE;            // resident W region
    const int tid = threadIdx.x, L = tid & 31, wid = tid >> 5;
    const int nt = blockIdx.x, mg = blockIdx.y, mbase = mg * 64;

    if (tid < 64) s_bias[tid] = g_bias[nt * 64 + tid];

    // --- resident W: 10 chunks x (hi,lo) planes, one cp.async group ---
#pragma unroll 4
    for (int i = 0; i < 80; i++) {
        int idx = tid + 128 * i;                       // 0..10239
        int pl = idx >> 9;                             // plane 0..19
        int rem = idx & 511, r = rem >> 3, ch = rem & 7;
        int s = pl >> 1, hl = pl & 1;
        const __half* src = (hl ? g_Wlo : g_Whi)
                          + (size_t)(nt * 64 + r) * KTOT + s * 64 + ch * 8;
        cpa16(wb + (uint32_t)pl * PLANE + r * ROWB + ch * 16, src);
    }
    CP_COMMIT();

    // --- prefetch x chunks 0,1 of t=0 ---
    {
        const __half* xr = g_Xh + ((size_t)0 * BB + mbase) * NIN;
        load_A(sb,          tid, xr,      NIN);
        load_A(sb + PLANE,  tid, xr + 64, NIN);
    }

    const int mwb = (wid & 1) * 32, nwb = (wid >> 1) * 32;
    const uint32_t aoff = (uint32_t)((((L >> 3) & 1) * 8 + (L & 7)) * ROWB + (L >> 4) * 16);
    const uint32_t boff = (uint32_t)(((L >> 4) * 8 + (L & 7)) * ROWB + ((L >> 3) & 1) * 16);

    // persistent cell state: thread -> (row = tid>>1, units nt*16 + (tid&1)*8 ..+7)
    float creg[8];
#pragma unroll
    for (int j = 0; j < 8; j++) creg[j] = 0.f;

    unsigned* barp = &g_bar;

#pragma unroll 1
    for (int t = 0; t < TT; t++) {
        const __half* hrow = g_Hh + ((size_t)t * BB + mbase) * NH;

        // h chunks 2,3 into buffers 2,3 (x0,x1 already in 0,1)
        load_A(sb + 2 * PLANE, tid, hrow,      NH);
        load_A(sb + 3 * PLANE, tid, hrow + 64, NH);

        float c[2][4][4];
#pragma unroll
        for (int a = 0; a < 2; a++)
#pragma unroll
            for (int b = 0; b < 4; b++)
#pragma unroll
                for (int d = 0; d < 4; d++) c[a][b][d] = 0.f;

#pragma unroll 1
        for (int s = 0; s < SK_CHUNKS; s++) {
            if (s <= 6)      asm volatile("cp.async.wait_group 3;" ::: "memory");
            else if (s == 7) asm volatile("cp.async.wait_group 2;" ::: "memory");
            else if (s == 8) asm volatile("cp.async.wait_group 1;" ::: "memory");
            else             asm volatile("cp.async.wait_group 0;" ::: "memory");
            __syncthreads();
            compute_chunk(sb + (uint32_t)(s & 3) * PLANE, wb + (uint32_t)s * 2 * PLANE,
                          mwb, nwb, aoff, boff, c);
            __syncthreads();
            if (s <= 5) {   // chunk s+4 (h cols (s+2)*64) into just-freed buffer
                load_A(sb + (uint32_t)(s & 3) * PLANE, tid, hrow + (s + 2) * 64, NH);
            }
        }

        // --- gates -> smem (buf0/1 region), stride 272 B/row ---
#pragma unroll
        for (int mt = 0; mt < 2; mt++)
#pragma unroll
            for (int j = 0; j < 4; j++) {
                int row = mwb + mt * 16 + (L >> 2);
                int col = nwb + j * 8 + 2 * (L & 3);
                *(float2*)(dyn + row * 272 + col * 4) = make_float2(c[mt][j][0], c[mt][j][1]);
                *(float2*)(dyn + (row + 8) * 272 + col * 4) = make_float2(c[mt][j][2], c[mt][j][3]);
            }
        __syncthreads();

        // --- cell update (c in registers), h -> global fp16 ---
        {
            const int row = tid >> 1;
            const int ub = (tid & 1) * 8;
            const int brow = mbase + row;
            __half* hh = g_Hh + ((size_t)(t + 1) * BB + brow) * NH + nt * 16 + ub;

            uint16_t hq[8];
#pragma unroll
            for (int j = 0; j < 8; j++) {
                float4 gv = *(const float4*)(dyn + row * 272 + (ub + j) * 16);
                float4 bb2 = *(const float4*)((const char*)s_bias + (ub + j) * 16);
                float iv = fsigmoid(gv.x + bb2.x);
                float fv = fsigmoid(gv.y + bb2.y);
                float gg = ftanh(gv.z + bb2.z);
                float ov = fsigmoid(gv.w + bb2.w);
                float cv = fv * creg[j] + iv * gg;
                creg[j] = cv;
                hq[j] = __half_as_ushort(__float2half_rn(ov * ftanh(cv)));
            }
            uint4 ph;
            ph.x = (uint32_t)hq[0] | ((uint32_t)hq[1] << 16);
            ph.y = (uint32_t)hq[2] | ((uint32_t)hq[3] << 16);
            ph.z = (uint32_t)hq[4] | ((uint32_t)hq[5] << 16);
            ph.w = (uint32_t)hq[6] | ((uint32_t)hq[7] << 16);
            *(uint4*)hh = ph;
        }
        __syncthreads();   // gates fully consumed before prefetch overwrites buf0/1

        if (t + 1 < TT) {
            // prefetch next step's x chunks (independent of h) — overlaps barrier
            const __half* xr = g_Xh + ((size_t)(t + 1) * BB + mbase) * NIN;
            load_A(sb,         tid, xr,      NIN);
            load_A(sb + PLANE, tid, xr + 64, NIN);

            // grid barrier: h_t (slot t+1) visible to all CTAs
            __threadfence();
            __syncthreads();
            if (tid == 0) {
                atomicAdd(barp, 1u);
                const unsigned target = 128u * (unsigned)(t + 1);
                unsigned v;
                unsigned long long guard = 0;
                do {
                    asm volatile("ld.acquire.gpu.global.u32 %0, [%1];" : "=r"(v) : "l"(barp));
                    if (v >= target) break;
                    asm volatile("nanosleep.u32 32;");
                    if (++guard > 200000000ULL) __trap();   // loud abort on deadlock
                } while (true);
            }
            __syncthreads();
        }
    }
}

// ---------------------------------------------------------------------------
// Classifier: out[131072,64] = hs @ W_cls^T + b_cls. grid 2048 x 128 thr.
// Stage = A plane + Whi + Wlo planes, double-buffered (3 groups/stage).
// ---------------------------------------------------------------------------
__global__ void __launch_bounds__(128) cls_kernel(const float* __restrict__ b_cls,
                                                  float* __restrict__ out) {
    extern __shared__ char dyn[];
    __shared__ float s_bias[64];

    const uint32_t sb = smem_u32(dyn);
    const int tid = threadIdx.x, L = tid & 31, wid = tid >> 5;
    const size_t mb = (size_t)blockIdx.x * 64;

    if (tid < 64) s_bias[tid] = b_cls[tid];

    const __half* a0 = g_Hh + (BB + mb) * NH;   // hs rows (skip slot 0)

    load_A(sb,             tid, a0,     NH);
    load_A(sb + PLANE,     tid, g_Wchi, NH);
    load_A(sb + 2 * PLANE, tid, g_Wclo, NH);

    float c[2][4][4];
#pragma unroll
    for (int a = 0; a < 2; a++)
#pragma unroll
        for (int b = 0; b < 4; b++)
#pragma unroll
            for (int d = 0; d < 4; d++) c[a][b][d] = 0.f;

    const int mwb = (wid & 1) * 32, nwb = (wid >> 1) * 32;
    const uint32_t aoff = (uint32_t)((((L >> 3) & 1) * 8 + (L & 7)) * ROWB + (L >> 4) * 16);
    const uint32_t boff = (uint32_t)(((L >> 4) * 8 + (L & 7)) * ROWB + ((L >> 3) & 1) * 16);

#pragma unroll 1
    for (int s = 0; s < CLS_CHUNKS; s++) {
        if (s + 1 < CLS_CHUNKS) {
            int sn = s + 1;
            uint32_t nb = sb + (sn & 1) * CLS_STAGE;
            load_A(nb,             tid, a0 + sn * 64,     NH);
            load_A(nb + PLANE,     tid, g_Wchi + sn * 64, NH);
            load_A(nb + 2 * PLANE, tid, g_Wclo + sn * 64, NH);
            asm volatile("cp.async.wait_group 3;" ::: "memory");
        } else {
            asm volatile("cp.async.wait_group 0;" ::: "memory");
        }
        __syncthreads();
        uint32_t base = sb + (s & 1) * CLS_STAGE;
        compute_chunk(base, base + PLANE, mwb, nwb, aoff, boff, c);
        __syncthreads();
    }

#pragma unroll
    for (int mt = 0; mt < 2; mt++)
#pragma unroll
        for (int j = 0; j < 4; j++) {
            int row = mwb + mt * 16 + (L >> 2);
            int col = nwb + j * 8 + 2 * (L & 3);
            float2 bb = *(const float2*)((const char*)s_bias + col * 4);
            float* op = out + (mb + row) * NOUT + col;
            *(float2*)op = make_float2(c[mt][j][0] + bb.x, c[mt][j][1] + bb.y);
            *(float2*)(op + 8 * NOUT) = make_float2(c[mt][j][2] + bb.x, c[mt][j][3] + bb.y);
        }
}

// ---------------------------------------------------------------------------
// Launch
// ---------------------------------------------------------------------------
extern "C" void kernel_launch(void* const* d_in, const int* in_sizes, int n_in,
                              void* d_out, int out_size) {
    const float* input = (const float*)d_in[0];
    const float* dtv   = (const float*)d_in[1];
    const float* W_ih  = (const float*)d_in[2];
    const float* W_hh  = (const float*)d_in[3];
    const float* b_ih  = (const float*)d_in[4];
    const float* b_hh  = (const float*)d_in[5];
    const float* W_cls = (const float*)d_in[6];
    const float* b_cls = (const float*)d_in[7];
    float* out = (float*)d_out;

    cudaFuncSetAttribute(persistent_step, cudaFuncAttributeMaxDynamicSharedMemorySize, PERS_SMEM);
    cudaFuncSetAttribute(cls_kernel, cudaFuncAttributeMaxDynamicSharedMemorySize, CLS_SMEM);

    prep_w<<<(NGATE * KTOT + 255) / 256, 256>>>(W_ih, W_hh, b_ih, b_hh);
    prep_wcls<<<(NOUT * NH + 255) / 256, 256>>>(W_cls);
    prep_x<<<(TT * BB * NIN + 255) / 256, 256>>>(input, dtv);
    prep_zero<<<(BB * NH + 255) / 256, 256>>>();

    persistent_step<<<dim3(32, 4), 128, PERS_SMEM>>>();
    cls_kernel<<<2048, 128, CLS_SMEM>>>(b_cls, out);
}

// round 8
// speedup vs baseline: 1.5748x; 1.1095x over previous
#include <cuda_runtime.h>
#include <cuda_fp16.h>
#include <cstdint>
#include <cstddef>

// ---------------------------------------------------------------------------
// Problem constants
// ---------------------------------------------------------------------------
#define TT    512
#define BB    256
#define NIN   128      // NINP (127 input + 1 dt)
#define NH    512      // NHID
#define NGATE 2048     // 4*NHID
#define KTOT  640      // NIN + NH
#define NOUT  64

// Tiling: CTA = 64 rows x 64 gate-cols, K chunks of 64.
// A (x,h) plain fp16; W resident split hi+lo; pass1 f32-accum, pass2 f16-accum.
#define ROWB   144             // smem row stride (64 fp16 = 128B + 16B pad)
#define PLANE  (64 * ROWB)     // 9216 B per 64x64 fp16 plane
#define SK_CHUNKS 10           // 640/64
#define CLS_CHUNKS 8           // 512/64
#define NABUF  4               // A pipeline depth
#define WREGION (SK_CHUNKS * 2 * PLANE)          // 184320 B resident W
#define PERS_SMEM (NABUF * PLANE + WREGION)      // 221184 B
#define CLS_STAGE (3 * PLANE)                    // A + Whi + Wlo
#define CLS_SMEM (2 * CLS_STAGE)                 // 55296 B

// ---------------------------------------------------------------------------
// Device scratch
// ---------------------------------------------------------------------------
__device__ __half g_Xh[(size_t)TT * BB * NIN];    // fp16 [x|dt]
__device__ __half g_Whi[(size_t)NGATE * KTOT];    // permuted: row 4j+g
__device__ __half g_Wlo[(size_t)NGATE * KTOT];
__device__ __half g_Wchi[(size_t)NOUT * NH];
__device__ __half g_Wclo[(size_t)NOUT * NH];
__device__ float  g_bias[NGATE];
__device__ __half g_Hh[(size_t)(TT + 1) * BB * NH];  // slot s = h_{s-1}
__device__ unsigned g_bar;                        // grid barrier counter

// ---------------------------------------------------------------------------
// Helpers
// ---------------------------------------------------------------------------
__device__ __forceinline__ uint32_t smem_u32(const void* p) {
    uint32_t a;
    asm("{ .reg .u64 t; cvta.to.shared.u64 t, %1; cvt.u32.u64 %0, t; }" : "=r"(a) : "l"(p));
    return a;
}

__device__ __forceinline__ void ldsm4(uint32_t addr, uint32_t r[4]) {
    asm volatile("ldmatrix.sync.aligned.m8n8.x4.shared.b16 {%0,%1,%2,%3}, [%4];"
                 : "=r"(r[0]), "=r"(r[1]), "=r"(r[2]), "=r"(r[3]) : "r"(addr));
}

__device__ __forceinline__ void mma16816(float c[4], const uint32_t a[4],
                                         uint32_t b0, uint32_t b1) {
    asm volatile("mma.sync.aligned.m16n8k16.row.col.f32.f16.f16.f32 "
                 "{%0,%1,%2,%3}, {%4,%5,%6,%7}, {%8,%9}, {%0,%1,%2,%3};"
                 : "+f"(c[0]), "+f"(c[1]), "+f"(c[2]), "+f"(c[3])
                 : "r"(a[0]), "r"(a[1]), "r"(a[2]), "r"(a[3]), "r"(b0), "r"(b1));
}

// fp16-accumulator variant: 2x HMMA rate; used for the small W-lo correction.
__device__ __forceinline__ void mma16816_f16(uint32_t c[2], const uint32_t a[4],
                                             uint32_t b0, uint32_t b1) {
    asm volatile("mma.sync.aligned.m16n8k16.row.col.f16.f16.f16.f16 "
                 "{%0,%1}, {%2,%3,%4,%5}, {%6,%7}, {%0,%1};"
                 : "+r"(c[0]), "+r"(c[1])
                 : "r"(a[0]), "r"(a[1]), "r"(a[2]), "r"(a[3]), "r"(b0), "r"(b1));
}

__device__ __forceinline__ void cpa16(uint32_t dst, const void* src) {
    asm volatile("cp.async.cg.shared.global [%0], [%1], 16;" :: "r"(dst), "l"(src));
}
#define CP_COMMIT() asm volatile("cp.async.commit_group;" ::: "memory")

__device__ __forceinline__ float fsigmoid(float x) {
    x = fminf(fmaxf(x, -30.f), 30.f);
    return 1.0f / (1.0f + __expf(-x));
}
__device__ __forceinline__ float ftanh(float x) {
    x = fminf(fmaxf(x, -15.f), 15.f);
    float e = __expf(-2.0f * x);
    return (1.0f - e) / (1.0f + e);
}

// Load one 64x64 fp16 plane via cp.async (one commit group).
__device__ __forceinline__ void load_A(uint32_t dst, int tid,
                                       const __half* src0, int astr) {
#pragma unroll
    for (int i = 0; i < 4; i++) {
        int idx = tid + 128 * i;               // 0..511
        int r = idx >> 3, ch = idx & 7;
        cpa16(dst + r * ROWB + ch * 16, src0 + (size_t)r * astr + ch * 8);
    }
    CP_COMMIT();
}

// One K=64 chunk: pass1 c += A*Whi (f32 accum), pass2 clo += A*Wlo (f16 accum).
__device__ __forceinline__ void compute_chunk(uint32_t abase, uint32_t wbase,
                                              int mwb, int nwb,
                                              uint32_t aoff, uint32_t boff,
                                              float c[2][4][4], uint32_t clo[2][4][2]) {
#pragma unroll
    for (int kk = 0; kk < 4; kk++) {
        uint32_t a[2][4], bhi[2][4], blo[2][4];
#pragma unroll
        for (int mt = 0; mt < 2; mt++)
            ldsm4(abase + (uint32_t)(mwb + mt * 16) * ROWB + kk * 32 + aoff, a[mt]);
#pragma unroll
        for (int q = 0; q < 2; q++) {
            uint32_t base = wbase + (uint32_t)(nwb + q * 16) * ROWB + kk * 32 + boff;
            ldsm4(base, bhi[q]);
            ldsm4(base + PLANE, blo[q]);
        }
#pragma unroll
        for (int mt = 0; mt < 2; mt++)
#pragma unroll
            for (int j = 0; j < 4; j++)
                mma16816(c[mt][j], a[mt], bhi[j >> 1][(j & 1) * 2], bhi[j >> 1][(j & 1) * 2 + 1]);
#pragma unroll
        for (int mt = 0; mt < 2; mt++)
#pragma unroll
            for (int j = 0; j < 4; j++)
                mma16816_f16(clo[mt][j], a[mt], blo[j >> 1][(j & 1) * 2], blo[j >> 1][(j & 1) * 2 + 1]);
    }
}

__device__ __forceinline__ void zero_acc(float c[2][4][4], uint32_t clo[2][4][2]) {
#pragma unroll
    for (int a = 0; a < 2; a++)
#pragma unroll
        for (int b = 0; b < 4; b++) {
#pragma unroll
            for (int d = 0; d < 4; d++) c[a][b][d] = 0.f;
            clo[a][b][0] = 0u; clo[a][b][1] = 0u;
        }
}

__device__ __forceinline__ void merge_lo(float c[2][4][4], const uint32_t clo[2][4][2]) {
#pragma unroll
    for (int a = 0; a < 2; a++)
#pragma unroll
        for (int b = 0; b < 4; b++) {
            float2 f0 = __half22float2(*(const __half2*)&clo[a][b][0]);
            float2 f1 = __half22float2(*(const __half2*)&clo[a][b][1]);
            c[a][b][0] += f0.x; c[a][b][1] += f0.y;
            c[a][b][2] += f1.x; c[a][b][3] += f1.y;
        }
}

// ---------------------------------------------------------------------------
// Prep kernels
// ---------------------------------------------------------------------------
__device__ __forceinline__ void split16(float v, __half* hi, __half* lo) {
    __half h = __float2half_rn(v);
    *hi = h;
    *lo = __float2half_rn(v - __half2float(h));
}

__global__ void prep_w(const float* __restrict__ W_ih, const float* __restrict__ W_hh,
                       const float* __restrict__ b_ih, const float* __restrict__ b_hh) {
    int idx = blockIdx.x * 256 + threadIdx.x;
    if (idx < NGATE * KTOT) {
        int p = idx / KTOT, k = idx - p * KTOT;
        int j = p >> 2, g = p & 3;
        int srow = g * NH + j;
        float v = (k < NIN) ? W_ih[(size_t)srow * NIN + k]
                            : W_hh[(size_t)srow * NH + (k - NIN)];
        split16(v, &g_Whi[idx], &g_Wlo[idx]);
    }
    if (idx < NGATE) {
        int j = idx >> 2, g = idx & 3;
        g_bias[idx] = b_ih[g * NH + j] + b_hh[g * NH + j];
    }
}

__global__ void prep_wcls(const float* __restrict__ W_cls) {
    int idx = blockIdx.x * 256 + threadIdx.x;
    if (idx < NOUT * NH) split16(W_cls[idx], &g_Wchi[idx], &g_Wclo[idx]);
}

__global__ void prep_x(const float* __restrict__ input, const float* __restrict__ dtv) {
    int idx = blockIdx.x * 256 + threadIdx.x;
    if (idx < TT * BB * NIN) {
        int k = idx & (NIN - 1);
        int tb = idx >> 7;
        float v = (k < NIN - 1) ? input[(size_t)tb * (NIN - 1) + k] : dtv[tb];
        g_Xh[idx] = __float2half_rn(v);
    }
}

__global__ void prep_zero() {
    int idx = blockIdx.x * 256 + threadIdx.x;
    if (idx == 0) g_bar = 0;
    if (idx < BB * NH) g_Hh[idx] = __float2half_rn(0.0f);   // h_{-1}
}

// ---------------------------------------------------------------------------
// Persistent kernel: all 512 LSTM steps in one launch.
// grid (32 n-tiles, 4 m-groups) = 128 CTAs (1/SM), 128 threads.
// W (hi+lo) resident in smem; c in registers; grid barrier between steps.
// x-only chunks (0,1) of step t+1 are COMPUTED between barrier-arrive and
// barrier-spin, hiding 2/10 of the MMA work plus load latency behind the sync.
// ---------------------------------------------------------------------------
__global__ void __launch_bounds__(128) persistent_step() {
    extern __shared__ char dyn[];
    __shared__ float s_bias[64];

    const uint32_t sb = smem_u32(dyn);                 // 4 A buffers
    const uint32_t wb = sb + NABUF * PLANE;            // resident W region
    const int tid = threadIdx.x, L = tid & 31, wid = tid >> 5;
    const int nt = blockIdx.x, mg = blockIdx.y, mbase = mg * 64;

    if (tid < 64) s_bias[tid] = g_bias[nt * 64 + tid];

    // --- resident W: 10 chunks x (hi,lo) planes, one cp.async group ---
#pragma unroll 4
    for (int i = 0; i < 80; i++) {
        int idx = tid + 128 * i;                       // 0..10239
        int pl = idx >> 9;                             // plane 0..19
        int rem = idx & 511, r = rem >> 3, ch = rem & 7;
        int s = pl >> 1, hl = pl & 1;
        const __half* src = (hl ? g_Wlo : g_Whi)
                          + (size_t)(nt * 64 + r) * KTOT + s * 64 + ch * 8;
        cpa16(wb + (uint32_t)pl * PLANE + r * ROWB + ch * 16, src);
    }
    CP_COMMIT();

    // --- x chunks 0,1 of t=0 ---
    {
        const __half* xr = g_Xh + (size_t)mbase * NIN;
        load_A(sb,         tid, xr,      NIN);
        load_A(sb + PLANE, tid, xr + 64, NIN);
    }

    const int mwb = (wid & 1) * 32, nwb = (wid >> 1) * 32;
    const uint32_t aoff = (uint32_t)((((L >> 3) & 1) * 8 + (L & 7)) * ROWB + (L >> 4) * 16);
    const uint32_t boff = (uint32_t)(((L >> 4) * 8 + (L & 7)) * ROWB + ((L >> 3) & 1) * 16);

    // persistent cell state: thread -> (row = tid>>1, units nt*16 + (tid&1)*8 ..+7)
    float creg[8];
#pragma unroll
    for (int j = 0; j < 8; j++) creg[j] = 0.f;

    unsigned* barp = &g_bar;

    float c[2][4][4];
    uint32_t clo[2][4][2];

    // pre-loop: W + x ready, compute chunks 0,1 of t=0
    asm volatile("cp.async.wait_group 0;" ::: "memory");
    __syncthreads();
    zero_acc(c, clo);
    compute_chunk(sb,         wb,             mwb, nwb, aoff, boff, c, clo);
    compute_chunk(sb + PLANE, wb + 2 * PLANE, mwb, nwb, aoff, boff, c, clo);
    __syncthreads();

#pragma unroll 1
    for (int t = 0; t < TT; t++) {
        const __half* hrow = g_Hh + ((size_t)t * BB + mbase) * NH;

        // h chunks 2,3,4,5 into bufs 2,3,0,1 (bufs 0,1 freed: chunks 0,1 done)
        load_A(sb + 2 * PLANE, tid, hrow,       NH);
        load_A(sb + 3 * PLANE, tid, hrow + 64,  NH);
        load_A(sb,             tid, hrow + 128, NH);
        load_A(sb + PLANE,     tid, hrow + 192, NH);

#pragma unroll 1
        for (int s = 2; s < SK_CHUNKS; s++) {
            if (s <= 6)      asm volatile("cp.async.wait_group 3;" ::: "memory");
            else if (s == 7) asm volatile("cp.async.wait_group 2;" ::: "memory");
            else if (s == 8) asm volatile("cp.async.wait_group 1;" ::: "memory");
            else             asm volatile("cp.async.wait_group 0;" ::: "memory");
            __syncthreads();
            compute_chunk(sb + (uint32_t)(s & 3) * PLANE, wb + (uint32_t)s * 2 * PLANE,
                          mwb, nwb, aoff, boff, c, clo);
            __syncthreads();
            if (s <= 5) {   // chunk s+4 (h cols (s+2)*64) into just-freed buffer
                load_A(sb + (uint32_t)(s & 3) * PLANE, tid, hrow + (s + 2) * 64, NH);
            }
        }

        merge_lo(c, clo);

        // --- gates -> smem (buf0/1 region), stride 272 B/row ---
#pragma unroll
        for (int mt = 0; mt < 2; mt++)
#pragma unroll
            for (int j = 0; j < 4; j++) {
                int row = mwb + mt * 16 + (L >> 2);
                int col = nwb + j * 8 + 2 * (L & 3);
                *(float2*)(dyn + row * 272 + col * 4) = make_float2(c[mt][j][0], c[mt][j][1]);
                *(float2*)(dyn + (row + 8) * 272 + col * 4) = make_float2(c[mt][j][2], c[mt][j][3]);
            }
        __syncthreads();

        // --- cell update (c in registers), h -> global fp16 ---
        {
            const int row = tid >> 1;
            const int ub = (tid & 1) * 8;
            const int brow = mbase + row;
            __half* hh = g_Hh + ((size_t)(t + 1) * BB + brow) * NH + nt * 16 + ub;

            uint16_t hq[8];
#pragma unroll
            for (int j = 0; j < 8; j++) {
                float4 gv = *(const float4*)(dyn + row * 272 + (ub + j) * 16);
                float4 bb2 = *(const float4*)((const char*)s_bias + (ub + j) * 16);
                float iv = fsigmoid(gv.x + bb2.x);
                float fv = fsigmoid(gv.y + bb2.y);
                float gg = ftanh(gv.z + bb2.z);
                float ov = fsigmoid(gv.w + bb2.w);
                float cv = fv * creg[j] + iv * gg;
                creg[j] = cv;
                hq[j] = __half_as_ushort(__float2half_rn(ov * ftanh(cv)));
            }
            uint4 ph;
            ph.x = (uint32_t)hq[0] | ((uint32_t)hq[1] << 16);
            ph.y = (uint32_t)hq[2] | ((uint32_t)hq[3] << 16);
            ph.z = (uint32_t)hq[4] | ((uint32_t)hq[5] << 16);
            ph.w = (uint32_t)hq[6] | ((uint32_t)hq[7] << 16);
            *(uint4*)hh = ph;
        }

        // h stores visible, then arrive EARLY; spin comes after useful work.
        __threadfence();
        __syncthreads();
        if (tid == 0) atomicAdd(barp, 1u);

        if (t + 1 < TT) {
            // load + compute next step's x chunks before spinning
            const __half* xr = g_Xh + ((size_t)(t + 1) * BB + mbase) * NIN;
            load_A(sb,         tid, xr,      NIN);
            load_A(sb + PLANE, tid, xr + 64, NIN);
            asm volatile("cp.async.wait_group 0;" ::: "memory");
            __syncthreads();
            zero_acc(c, clo);
            compute_chunk(sb,         wb,             mwb, nwb, aoff, boff, c, clo);
            compute_chunk(sb + PLANE, wb + 2 * PLANE, mwb, nwb, aoff, boff, c, clo);

            // grid barrier: h_t (slot t+1) visible to all CTAs
            if (tid == 0) {
                const unsigned target = 128u * (unsigned)(t + 1);
                unsigned v;
                unsigned long long guard = 0;
                do {
                    asm volatile("ld.acquire.gpu.global.u32 %0, [%1];" : "=r"(v) : "l"(barp));
                    if (v >= target) break;
                    if (++guard > 400000000ULL) __trap();   // loud abort on deadlock
                } while (true);
            }
            __syncthreads();
        }
    }
}

// ---------------------------------------------------------------------------
// Classifier: out[131072,64] = hs @ W_cls^T + b_cls. grid 2048 x 128 thr.
// Stage = A plane + Whi + Wlo planes, double-buffered (3 groups/stage).
// ---------------------------------------------------------------------------
__global__ void __launch_bounds__(128) cls_kernel(const float* __restrict__ b_cls,
                                                  float* __restrict__ out) {
    extern __shared__ char dyn[];
    __shared__ float s_bias[64];

    const uint32_t sb = smem_u32(dyn);
    const int tid = threadIdx.x, L = tid & 31, wid = tid >> 5;
    const size_t mb = (size_t)blockIdx.x * 64;

    if (tid < 64) s_bias[tid] = b_cls[tid];

    const __half* a0 = g_Hh + (BB + mb) * NH;   // hs rows (skip slot 0)

    load_A(sb,             tid, a0,     NH);
    load_A(sb + PLANE,     tid, g_Wchi, NH);
    load_A(sb + 2 * PLANE, tid, g_Wclo, NH);

    float c[2][4][4];
    uint32_t clo[2][4][2];
    zero_acc(c, clo);

    const int mwb = (wid & 1) * 32, nwb = (wid >> 1) * 32;
    const uint32_t aoff = (uint32_t)((((L >> 3) & 1) * 8 + (L & 7)) * ROWB + (L >> 4) * 16);
    const uint32_t boff = (uint32_t)(((L >> 4) * 8 + (L & 7)) * ROWB + ((L >> 3) & 1) * 16);

#pragma unroll 1
    for (int s = 0; s < CLS_CHUNKS; s++) {
        if (s + 1 < CLS_CHUNKS) {
            int sn = s + 1;
            uint32_t nb = sb + (sn & 1) * CLS_STAGE;
            load_A(nb,             tid, a0 + sn * 64,     NH);
            load_A(nb + PLANE,     tid, g_Wchi + sn * 64, NH);
            load_A(nb + 2 * PLANE, tid, g_Wclo + sn * 64, NH);
            asm volatile("cp.async.wait_group 3;" ::: "memory");
        } else {
            asm volatile("cp.async.wait_group 0;" ::: "memory");
        }
        __syncthreads();
        uint32_t base = sb + (s & 1) * CLS_STAGE;
        compute_chunk(base, base + PLANE, mwb, nwb, aoff, boff, c, clo);
        __syncthreads();
    }

    merge_lo(c, clo);

#pragma unroll
    for (int mt = 0; mt < 2; mt++)
#pragma unroll
        for (int j = 0; j < 4; j++) {
            int row = mwb + mt * 16 + (L >> 2);
            int col = nwb + j * 8 + 2 * (L & 3);
            float2 bb = *(const float2*)((const char*)s_bias + col * 4);
            float* op = out + (mb + row) * NOUT + col;
            *(float2*)op = make_float2(c[mt][j][0] + bb.x, c[mt][j][1] + bb.y);
            *(float2*)(op + 8 * NOUT) = make_float2(c[mt][j][2] + bb.x, c[mt][j][3] + bb.y);
        }
}

// ---------------------------------------------------------------------------
// Launch
// ---------------------------------------------------------------------------
extern "C" void kernel_launch(void* const* d_in, const int* in_sizes, int n_in,
                              void* d_out, int out_size) {
    const float* input = (const float*)d_in[0];
    const float* dtv   = (const float*)d_in[1];
    const float* W_ih  = (const float*)d_in[2];
    const float* W_hh  = (const float*)d_in[3];
    const float* b_ih  = (const float*)d_in[4];
    const float* b_hh  = (const float*)d_in[5];
    const float* W_cls = (const float*)d_in[6];
    const float* b_cls = (const float*)d_in[7];
    float* out = (float*)d_out;

    cudaFuncSetAttribute(persistent_step, cudaFuncAttributeMaxDynamicSharedMemorySize, PERS_SMEM);
    cudaFuncSetAttribute(cls_kernel, cudaFuncAttributeMaxDynamicSharedMemorySize, CLS_SMEM);

    prep_w<<<(NGATE * KTOT + 255) / 256, 256>>>(W_ih, W_hh, b_ih, b_hh);
    prep_wcls<<<(NOUT * NH + 255) / 256, 256>>>(W_cls);
    prep_x<<<(TT * BB * NIN + 255) / 256, 256>>>(input, dtv);
    prep_zero<<<(BB * NH + 255) / 256, 256>>>();

    persistent_step<<<dim3(32, 4), 128, PERS_SMEM>>>();
    cls_kernel<<<2048, 128, CLS_SMEM>>>(b_cls, out);
}

// round 10
// speedup vs baseline: 1.6447x; 1.0444x over previous
#include <cuda_runtime.h>
#include <cuda_fp16.h>
#include <cstdint>
#include <cstddef>

// ---------------------------------------------------------------------------
// Problem constants
// ---------------------------------------------------------------------------
#define TT    512
#define BB    256
#define NIN   128      // NINP (127 input + 1 dt)
#define NH    512      // NHID
#define NGATE 2048     // 4*NHID
#define KTOT  640      // NIN + NH
#define NOUT  64

// Tiling: CTA = 64 rows x 64 gate-cols, K chunks of 64, 256 threads (8 warps,
// warp tile 16m x 32n). A (x,h) plain fp16; W resident hi+lo; pass1 f32-accum,
// pass2 (W-lo correction) f16-accum.
#define ROWB   144             // smem row stride (64 fp16 = 128B + 16B pad)
#define PLANE  (64 * ROWB)     // 9216 B per 64x64 fp16 plane
#define SK_CHUNKS 10           // 640/64
#define CLS_CHUNKS 8           // 512/64
#define NABUF  4               // A pipeline depth
#define WREGION (SK_CHUNKS * 2 * PLANE)          // 184320 B resident W
#define PERS_SMEM (NABUF * PLANE + WREGION)      // 221184 B
#define CLS_STAGE (3 * PLANE)                    // A + Whi + Wlo
#define CLS_SMEM (2 * CLS_STAGE)                 // 55296 B

// ---------------------------------------------------------------------------
// Device scratch
// ---------------------------------------------------------------------------
__device__ __half g_Xh[(size_t)TT * BB * NIN];    // fp16 [x|dt]
__device__ __half g_Whi[(size_t)NGATE * KTOT];    // permuted: row 4j+g
__device__ __half g_Wlo[(size_t)NGATE * KTOT];
__device__ __half g_Wchi[(size_t)NOUT * NH];
__device__ __half g_Wclo[(size_t)NOUT * NH];
__device__ float  g_bias[NGATE];
__device__ __half g_Hh[(size_t)(TT + 1) * BB * NH];  // slot s = h_{s-1}
__device__ unsigned g_barA[128];                  // 4 per-mg barrier counters (stride 32)

// ---------------------------------------------------------------------------
// Helpers
// ---------------------------------------------------------------------------
__device__ __forceinline__ uint32_t smem_u32(const void* p) {
    uint32_t a;
    asm("{ .reg .u64 t; cvta.to.shared.u64 t, %1; cvt.u32.u64 %0, t; }" : "=r"(a) : "l"(p));
    return a;
}

__device__ __forceinline__ void ldsm4(uint32_t addr, uint32_t r[4]) {
    asm volatile("ldmatrix.sync.aligned.m8n8.x4.shared.b16 {%0,%1,%2,%3}, [%4];"
                 : "=r"(r[0]), "=r"(r[1]), "=r"(r[2]), "=r"(r[3]) : "r"(addr));
}

__device__ __forceinline__ void mma16816(float c[4], const uint32_t a[4],
                                         uint32_t b0, uint32_t b1) {
    asm volatile("mma.sync.aligned.m16n8k16.row.col.f32.f16.f16.f32 "
                 "{%0,%1,%2,%3}, {%4,%5,%6,%7}, {%8,%9}, {%0,%1,%2,%3};"
                 : "+f"(c[0]), "+f"(c[1]), "+f"(c[2]), "+f"(c[3])
                 : "r"(a[0]), "r"(a[1]), "r"(a[2]), "r"(a[3]), "r"(b0), "r"(b1));
}

// fp16-accumulator variant (2x HMMA rate) for the small W-lo correction.
__device__ __forceinline__ void mma16816_f16(uint32_t c[2], const uint32_t a[4],
                                             uint32_t b0, uint32_t b1) {
    asm volatile("mma.sync.aligned.m16n8k16.row.col.f16.f16.f16.f16 "
                 "{%0,%1}, {%2,%3,%4,%5}, {%6,%7}, {%0,%1};"
                 : "+r"(c[0]), "+r"(c[1])
                 : "r"(a[0]), "r"(a[1]), "r"(a[2]), "r"(a[3]), "r"(b0), "r"(b1));
}

__device__ __forceinline__ void cpa16(uint32_t dst, const void* src) {
    asm volatile("cp.async.cg.shared.global [%0], [%1], 16;" :: "r"(dst), "l"(src));
}
#define CP_COMMIT() asm volatile("cp.async.commit_group;" ::: "memory")

__device__ __forceinline__ float fsigmoid(float x) {
    x = fminf(fmaxf(x, -30.f), 30.f);
    return 1.0f / (1.0f + __expf(-x));
}
__device__ __forceinline__ float ftanh(float x) {
    x = fminf(fmaxf(x, -15.f), 15.f);
    float e = __expf(-2.0f * x);
    return (1.0f - e) / (1.0f + e);
}

// Load one 64x64 fp16 plane via cp.async, 256 threads (one commit group).
__device__ __forceinline__ void load_A(uint32_t dst, int tid,
                                       const __half* src0, int astr) {
#pragma unroll
    for (int i = 0; i < 2; i++) {
        int idx = tid + 256 * i;               // 0..511
        int r = idx >> 3, ch = idx & 7;
        cpa16(dst + r * ROWB + ch * 16, src0 + (size_t)r * astr + ch * 8);
    }
    CP_COMMIT();
}

// One K=64 chunk, warp tile 16m x 32n:
// pass1 c += A*Whi (f32 accum), pass2 clo += A*Wlo (f16 accum).
__device__ __forceinline__ void compute_chunk(uint32_t abase, uint32_t wbase,
                                              int mwb, int nwb,
                                              uint32_t aoff, uint32_t boff,
                                              float c[4][4], uint32_t clo[4][2]) {
#pragma unroll
    for (int kk = 0; kk < 4; kk++) {
        uint32_t a[4], bhi[2][4], blo[2][4];
        ldsm4(abase + (uint32_t)mwb * ROWB + kk * 32 + aoff, a);
#pragma unroll
        for (int q = 0; q < 2; q++) {
            uint32_t base = wbase + (uint32_t)(nwb + q * 16) * ROWB + kk * 32 + boff;
            ldsm4(base, bhi[q]);
            ldsm4(base + PLANE, blo[q]);
        }
#pragma unroll
        for (int j = 0; j < 4; j++)
            mma16816(c[j], a, bhi[j >> 1][(j & 1) * 2], bhi[j >> 1][(j & 1) * 2 + 1]);
#pragma unroll
        for (int j = 0; j < 4; j++)
            mma16816_f16(clo[j], a, blo[j >> 1][(j & 1) * 2], blo[j >> 1][(j & 1) * 2 + 1]);
    }
}

__device__ __forceinline__ void zero_acc(float c[4][4], uint32_t clo[4][2]) {
#pragma unroll
    for (int b = 0; b < 4; b++) {
#pragma unroll
        for (int d = 0; d < 4; d++) c[b][d] = 0.f;
        clo[b][0] = 0u; clo[b][1] = 0u;
    }
}

__device__ __forceinline__ void merge_lo(float c[4][4], const uint32_t clo[4][2]) {
#pragma unroll
    for (int b = 0; b < 4; b++) {
        float2 f0 = __half22float2(*(const __half2*)&clo[b][0]);
        float2 f1 = __half22float2(*(const __half2*)&clo[b][1]);
        c[b][0] += f0.x; c[b][1] += f0.y;
        c[b][2] += f1.x; c[b][3] += f1.y;
    }
}

// ---------------------------------------------------------------------------
// Prep kernels
// ---------------------------------------------------------------------------
__device__ __forceinline__ void split16(float v, __half* hi, __half* lo) {
    __half h = __float2half_rn(v);
    *hi = h;
    *lo = __float2half_rn(v - __half2float(h));
}

__global__ void prep_w(const float* __restrict__ W_ih, const float* __restrict__ W_hh,
                       const float* __restrict__ b_ih, const float* __restrict__ b_hh) {
    int idx = blockIdx.x * 256 + threadIdx.x;
    if (idx < NGATE * KTOT) {
        int p = idx / KTOT, k = idx - p * KTOT;
        int j = p >> 2, g = p & 3;
        int srow = g * NH + j;
        float v = (k < NIN) ? W_ih[(size_t)srow * NIN + k]
                            : W_hh[(size_t)srow * NH + (k - NIN)];
        split16(v, &g_Whi[idx], &g_Wlo[idx]);
    }
    if (idx < NGATE) {
        int j = idx >> 2, g = idx & 3;
        g_bias[idx] = b_ih[g * NH + j] + b_hh[g * NH + j];
    }
}

__global__ void prep_wcls(const float* __restrict__ W_cls) {
    int idx = blockIdx.x * 256 + threadIdx.x;
    if (idx < NOUT * NH) split16(W_cls[idx], &g_Wchi[idx], &g_Wclo[idx]);
}

__global__ void prep_x(const float* __restrict__ input, const float* __restrict__ dtv) {
    int idx = blockIdx.x * 256 + threadIdx.x;
    if (idx < TT * BB * NIN) {
        int k = idx & (NIN - 1);
        int tb = idx >> 7;
        float v = (k < NIN - 1) ? input[(size_t)tb * (NIN - 1) + k] : dtv[tb];
        g_Xh[idx] = __float2half_rn(v);
    }
}

__global__ void prep_zero() {
    int idx = blockIdx.x * 256 + threadIdx.x;
    if (idx < 128) g_barA[idx] = 0;
    if (idx < BB * NH) g_Hh[idx] = __float2half_rn(0.0f);   // h_{-1}
}

// ---------------------------------------------------------------------------
// Persistent kernel: all 512 LSTM steps in one launch.
// grid (32 n-tiles, 4 m-groups) = 128 CTAs (1/SM), 256 threads (8 warps,
// 2/SMSP for latency hiding). W resident in smem; c in registers.
// Per-m-group barriers (32 CTAs each — only CTAs sharing h rows sync).
// x-only chunks (0,1) of step t+1 computed between barrier-arrive and spin.
// ---------------------------------------------------------------------------
__global__ void __launch_bounds__(256) persistent_step() {
    extern __shared__ char dyn[];
    __shared__ float s_bias[64];

    const uint32_t sb = smem_u32(dyn);                 // 4 A buffers
    const uint32_t wb = sb + NABUF * PLANE;            // resident W region
    const int tid = threadIdx.x, L = tid & 31, wid = tid >> 5;
    const int nt = blockIdx.x, mg = blockIdx.y, mbase = mg * 64;

    if (tid < 64) s_bias[tid] = g_bias[nt * 64 + tid];

    // --- resident W: 10 chunks x (hi,lo) planes, one cp.async group ---
#pragma unroll 4
    for (int i = 0; i < 40; i++) {
        int idx = tid + 256 * i;                       // 0..10239
        int pl = idx >> 9;                             // plane 0..19
        int rem = idx & 511, r = rem >> 3, ch = rem & 7;
        int s = pl >> 1, hl = pl & 1;
        const __half* src = (hl ? g_Wlo : g_Whi)
                          + (size_t)(nt * 64 + r) * KTOT + s * 64 + ch * 8;
        cpa16(wb + (uint32_t)pl * PLANE + r * ROWB + ch * 16, src);
    }
    CP_COMMIT();

    // --- x chunks 0,1 of t=0 ---
    {
        const __half* xr = g_Xh + (size_t)mbase * NIN;
        load_A(sb,         tid, xr,      NIN);
        load_A(sb + PLANE, tid, xr + 64, NIN);
    }

    // 8 warps: warp tile 16m x 32n.  mwb = (wid&3)*16, nwb = (wid>>2)*32
    const int mwb = (wid & 3) * 16, nwb = (wid >> 2) * 32;
    const uint32_t aoff = (uint32_t)((((L >> 3) & 1) * 8 + (L & 7)) * ROWB + (L >> 4) * 16);
    const uint32_t boff = (uint32_t)(((L >> 4) * 8 + (L & 7)) * ROWB + ((L >> 3) & 1) * 16);

    // persistent cell state: thread -> (row = tid>>2, units nt*16 + (tid&3)*4 ..+3)
    float creg[4];
#pragma unroll
    for (int j = 0; j < 4; j++) creg[j] = 0.f;

    unsigned* barp = &g_barA[mg * 32];

    float c[4][4];
    uint32_t clo[4][2];

    // pre-loop: W + x ready, compute chunks 0,1 of t=0
    asm volatile("cp.async.wait_group 0;" ::: "memory");
    __syncthreads();
    zero_acc(c, clo);
    compute_chunk(sb,         wb,             mwb, nwb, aoff, boff, c, clo);
    compute_chunk(sb + PLANE, wb + 2 * PLANE, mwb, nwb, aoff, boff, c, clo);
    __syncthreads();

#pragma unroll 1
    for (int t = 0; t < TT; t++) {
        const __half* hrow = g_Hh + ((size_t)t * BB + mbase) * NH;

        // h chunks 2,3,4,5 into bufs 2,3,0,1 (bufs 0,1 freed: chunks 0,1 done)
        load_A(sb + 2 * PLANE, tid, hrow,       NH);
        load_A(sb + 3 * PLANE, tid, hrow + 64,  NH);
        load_A(sb,             tid, hrow + 128, NH);
        load_A(sb + PLANE,     tid, hrow + 192, NH);

#pragma unroll 1
        for (int s = 2; s < SK_CHUNKS; s++) {
            if (s <= 6)      asm volatile("cp.async.wait_group 3;" ::: "memory");
            else if (s == 7) asm volatile("cp.async.wait_group 2;" ::: "memory");
            else if (s == 8) asm volatile("cp.async.wait_group 1;" ::: "memory");
            else             asm volatile("cp.async.wait_group 0;" ::: "memory");
            __syncthreads();
            compute_chunk(sb + (uint32_t)(s & 3) * PLANE, wb + (uint32_t)s * 2 * PLANE,
                          mwb, nwb, aoff, boff, c, clo);
            __syncthreads();
            if (s <= 5) {   // chunk s+4 (h cols (s+2)*64) into just-freed buffer
                load_A(sb + (uint32_t)(s & 3) * PLANE, tid, hrow + (s + 2) * 64, NH);
            }
        }

        merge_lo(c, clo);

        // --- gates -> smem (buf0/1 region), stride 272 B/row ---
#pragma unroll
        for (int j = 0; j < 4; j++) {
            int row = mwb + (L >> 2);
            int col = nwb + j * 8 + 2 * (L & 3);
            *(float2*)(dyn + row * 272 + col * 4) = make_float2(c[j][0], c[j][1]);
            *(float2*)(dyn + (row + 8) * 272 + col * 4) = make_float2(c[j][2], c[j][3]);
        }
        __syncthreads();

        // --- cell update (c in registers), h -> global fp16 ---
        {
            const int row = tid >> 2;              // 0..63
            const int ub = (tid & 3) * 4;          // 0,4,8,12
            const int brow = mbase + row;
            __half* hh = g_Hh + ((size_t)(t + 1) * BB + brow) * NH + nt * 16 + ub;

            uint16_t hq[4];
#pragma unroll
            for (int j = 0; j < 4; j++) {
                float4 gv = *(const float4*)(dyn + row * 272 + (ub + j) * 16);
                float4 bb2 = *(const float4*)((const char*)s_bias + (ub + j) * 16);
                float iv = fsigmoid(gv.x + bb2.x);
                float fv = fsigmoid(gv.y + bb2.y);
                float gg = ftanh(gv.z + bb2.z);
                float ov = fsigmoid(gv.w + bb2.w);
                float cv = fv * creg[j] + iv * gg;
                creg[j] = cv;
                hq[j] = __half_as_ushort(__float2half_rn(ov * ftanh(cv)));
            }
            uint2 ph;
            ph.x = (uint32_t)hq[0] | ((uint32_t)hq[1] << 16);
            ph.y = (uint32_t)hq[2] | ((uint32_t)hq[3] << 16);
            *(uint2*)hh = ph;
        }

        // h stores visible, then arrive EARLY; spin comes after useful work.
        __threadfence();
        __syncthreads();
        if (tid == 0) atomicAdd(barp, 1u);

        if (t + 1 < TT) {
            // load + compute next step's x chunks before spinning
            const __half* xr = g_Xh + ((size_t)(t + 1) * BB + mbase) * NIN;
            load_A(sb,         tid, xr,      NIN);
            load_A(sb + PLANE, tid, xr + 64, NIN);
            asm volatile("cp.async.wait_group 0;" ::: "memory");
            __syncthreads();
            zero_acc(c, clo);
            compute_chunk(sb,         wb,             mwb, nwb, aoff, boff, c, clo);
            compute_chunk(sb + PLANE, wb + 2 * PLANE, mwb, nwb, aoff, boff, c, clo);

            // per-mg barrier: h_t rows of this m-group visible to its 32 CTAs
            if (tid == 0) {
                const unsigned target = 32u * (unsigned)(t + 1);
                unsigned v;
                unsigned long long guard = 0;
                do {
                    asm volatile("ld.acquire.gpu.global.u32 %0, [%1];" : "=r"(v) : "l"(barp));
                    if (v >= target) break;
                    if (++guard > 400000000ULL) __trap();   // loud abort on deadlock
                } while (true);
            }
            __syncthreads();
        }
    }
}

// ---------------------------------------------------------------------------
// Classifier: out[131072,64] = hs @ W_cls^T + b_cls. grid 2048 x 256 thr.
// Stage = A plane + Whi + Wlo planes, double-buffered (3 groups/stage).
// ---------------------------------------------------------------------------
__global__ void __launch_bounds__(256) cls_kernel(const float* __restrict__ b_cls,
                                                  float* __restrict__ out) {
    extern __shared__ char dyn[];
    __shared__ float s_bias[64];

    const uint32_t sb = smem_u32(dyn);
    const int tid = threadIdx.x, L = tid & 31, wid = tid >> 5;
    const size_t mb = (size_t)blockIdx.x * 64;

    if (tid < 64) s_bias[tid] = b_cls[tid];

    const __half* a0 = g_Hh + (BB + mb) * NH;   // hs rows (skip slot 0)

    load_A(sb,             tid, a0,     NH);
    load_A(sb + PLANE,     tid, g_Wchi, NH);
    load_A(sb + 2 * PLANE, tid, g_Wclo, NH);

    float c[4][4];
    uint32_t clo[4][2];
    zero_acc(c, clo);

    const int mwb = (wid & 3) * 16, nwb = (wid >> 2) * 32;
    const uint32_t aoff = (uint32_t)((((L >> 3) & 1) * 8 + (L & 7)) * ROWB + (L >> 4) * 16);
    const uint32_t boff = (uint32_t)(((L >> 4) * 8 + (L & 7)) * ROWB + ((L >> 3) & 1) * 16);

#pragma unroll 1
    for (int s = 0; s < CLS_CHUNKS; s++) {
        if (s + 1 < CLS_CHUNKS) {
            int sn = s + 1;
            uint32_t nb = sb + (sn & 1) * CLS_STAGE;
            load_A(nb,             tid, a0 + sn * 64,     NH);
            load_A(nb + PLANE,     tid, g_Wchi + sn * 64, NH);
            load_A(nb + 2 * PLANE, tid, g_Wclo + sn * 64, NH);
            asm volatile("cp.async.wait_group 3;" ::: "memory");
        } else {
            asm volatile("cp.async.wait_group 0;" ::: "memory");
        }
        __syncthreads();
        uint32_t base = sb + (s & 1) * CLS_STAGE;
        compute_chunk(base, base + PLANE, mwb, nwb, aoff, boff, c, clo);
        __syncthreads();
    }

    merge_lo(c, clo);

#pragma unroll
    for (int j = 0; j < 4; j++) {
        int row = mwb + (L >> 2);
        int col = nwb + j * 8 + 2 * (L & 3);
        float2 bb = *(const float2*)((const char*)s_bias + col * 4);
        float* op = out + (mb + row) * NOUT + col;
        *(float2*)op = make_float2(c[j][0] + bb.x, c[j][1] + bb.y);
        *(float2*)(op + 8 * NOUT) = make_float2(c[j][2] + bb.x, c[j][3] + bb.y);
    }
}

// ---------------------------------------------------------------------------
// Launch
// ---------------------------------------------------------------------------
extern "C" void kernel_launch(void* const* d_in, const int* in_sizes, int n_in,
                              void* d_out, int out_size) {
    const float* input = (const float*)d_in[0];
    const float* dtv   = (const float*)d_in[1];
    const float* W_ih  = (const float*)d_in[2];
    const float* W_hh  = (const float*)d_in[3];
    const float* b_ih  = (const float*)d_in[4];
    const float* b_hh  = (const float*)d_in[5];
    const float* W_cls = (const float*)d_in[6];
    const float* b_cls = (const float*)d_in[7];
    float* out = (float*)d_out;

    cudaFuncSetAttribute(persistent_step, cudaFuncAttributeMaxDynamicSharedMemorySize, PERS_SMEM);
    cudaFuncSetAttribute(cls_kernel, cudaFuncAttributeMaxDynamicSharedMemorySize, CLS_SMEM);

    prep_w<<<(NGATE * KTOT + 255) / 256, 256>>>(W_ih, W_hh, b_ih, b_hh);
    prep_wcls<<<(NOUT * NH + 255) / 256, 256>>>(W_cls);
    prep_x<<<(TT * BB * NIN + 255) / 256, 256>>>(input, dtv);
    prep_zero<<<(BB * NH + 255) / 256, 256>>>();

    persistent_step<<<dim3(32, 4), 256, PERS_SMEM>>>();
    cls_kernel<<<2048, 256, CLS_SMEM>>>(b_cls, out);
}

// round 11
// speedup vs baseline: 1.8974x; 1.1536x over previous
#include <cuda_runtime.h>
#include <cuda_fp16.h>
#include <cstdint>
#include <cstddef>

// ---------------------------------------------------------------------------
// Problem constants
// ---------------------------------------------------------------------------
#define TT    512
#define BB    256
#define NIN   128      // NINP (127 input + 1 dt)
#define NH    512      // NHID
#define NGATE 2048     // 4*NHID
#define KTOT  640      // NIN + NH
#define NOUT  64

// Tiling: CTA = 64 rows x 64 gate-cols, K chunks of 64, 256 threads (8 warps,
// warp tile 16m x 32n). A (x,h) plain fp16; W resident hi+lo; pass1 f32-accum,
// pass2 (W-lo correction) f16-accum.
#define ROWB   144             // smem row stride (64 fp16 = 128B + 16B pad)
#define PLANE  (64 * ROWB)     // 9216 B per 64x64 fp16 plane
#define SK_CHUNKS 10           // 640/64
#define CLS_CHUNKS 8           // 512/64
#define NABUF  5               // A pipeline depth (chunk s -> buf s%5)
#define WREGION (SK_CHUNKS * 2 * PLANE)          // 184320 B resident W
#define PERS_SMEM (NABUF * PLANE + WREGION)      // 230400 B (<= 227KB cap)
#define CLS_STAGE (3 * PLANE)                    // A + Whi + Wlo
#define CLS_SMEM (2 * CLS_STAGE)                 // 55296 B

// ---------------------------------------------------------------------------
// Device scratch
// ---------------------------------------------------------------------------
__device__ __half g_Xh[(size_t)TT * BB * NIN];    // fp16 [x|dt]
__device__ __half g_Whi[(size_t)NGATE * KTOT];    // permuted: row 4j+g
__device__ __half g_Wlo[(size_t)NGATE * KTOT];
__device__ __half g_Wchi[(size_t)NOUT * NH];
__device__ __half g_Wclo[(size_t)NOUT * NH];
__device__ float  g_bias[NGATE];
__device__ __half g_Hh[(size_t)(TT + 1) * BB * NH];  // slot s = h_{s-1}
__device__ unsigned g_barA[128];                  // 4 per-mg counters (stride 32)

// ---------------------------------------------------------------------------
// Helpers
// ---------------------------------------------------------------------------
__device__ __forceinline__ uint32_t smem_u32(const void* p) {
    uint32_t a;
    asm("{ .reg .u64 t; cvta.to.shared.u64 t, %1; cvt.u32.u64 %0, t; }" : "=r"(a) : "l"(p));
    return a;
}

__device__ __forceinline__ void ldsm4(uint32_t addr, uint32_t r[4]) {
    asm volatile("ldmatrix.sync.aligned.m8n8.x4.shared.b16 {%0,%1,%2,%3}, [%4];"
                 : "=r"(r[0]), "=r"(r[1]), "=r"(r[2]), "=r"(r[3]) : "r"(addr));
}

__device__ __forceinline__ void mma16816(float c[4], const uint32_t a[4],
                                         uint32_t b0, uint32_t b1) {
    asm volatile("mma.sync.aligned.m16n8k16.row.col.f32.f16.f16.f32 "
                 "{%0,%1,%2,%3}, {%4,%5,%6,%7}, {%8,%9}, {%0,%1,%2,%3};"
                 : "+f"(c[0]), "+f"(c[1]), "+f"(c[2]), "+f"(c[3])
                 : "r"(a[0]), "r"(a[1]), "r"(a[2]), "r"(a[3]), "r"(b0), "r"(b1));
}

// fp16-accumulator variant (2x HMMA rate) for the small W-lo correction.
__device__ __forceinline__ void mma16816_f16(uint32_t c[2], const uint32_t a[4],
                                             uint32_t b0, uint32_t b1) {
    asm volatile("mma.sync.aligned.m16n8k16.row.col.f16.f16.f16.f16 "
                 "{%0,%1}, {%2,%3,%4,%5}, {%6,%7}, {%0,%1};"
                 : "+r"(c[0]), "+r"(c[1])
                 : "r"(a[0]), "r"(a[1]), "r"(a[2]), "r"(a[3]), "r"(b0), "r"(b1));
}

__device__ __forceinline__ void cpa16(uint32_t dst, const void* src) {
    asm volatile("cp.async.cg.shared.global [%0], [%1], 16;" :: "r"(dst), "l"(src));
}
#define CP_COMMIT() asm volatile("cp.async.commit_group;" ::: "memory")

__device__ __forceinline__ float fsigmoid(float x) {
    x = fminf(fmaxf(x, -30.f), 30.f);
    return 1.0f / (1.0f + __expf(-x));
}
__device__ __forceinline__ float ftanh(float x) {
    x = fminf(fmaxf(x, -15.f), 15.f);
    float e = __expf(-2.0f * x);
    return (1.0f - e) / (1.0f + e);
}

// Load one 64x64 fp16 plane via cp.async, 256 threads (one commit group).
__device__ __forceinline__ void load_A(uint32_t dst, int tid,
                                       const __half* src0, int astr) {
#pragma unroll
    for (int i = 0; i < 2; i++) {
        int idx = tid + 256 * i;               // 0..511
        int r = idx >> 3, ch = idx & 7;
        cpa16(dst + r * ROWB + ch * 16, src0 + (size_t)r * astr + ch * 8);
    }
    CP_COMMIT();
}

// One K=64 chunk, warp tile 16m x 32n:
// pass1 c += A*Whi (f32 accum), pass2 clo += A*Wlo (f16 accum).
__device__ __forceinline__ void compute_chunk(uint32_t abase, uint32_t wbase,
                                              int mwb, int nwb,
                                              uint32_t aoff, uint32_t boff,
                                              float c[4][4], uint32_t clo[4][2]) {
#pragma unroll
    for (int kk = 0; kk < 4; kk++) {
        uint32_t a[4], bhi[2][4], blo[2][4];
        ldsm4(abase + (uint32_t)mwb * ROWB + kk * 32 + aoff, a);
#pragma unroll
        for (int q = 0; q < 2; q++) {
            uint32_t base = wbase + (uint32_t)(nwb + q * 16) * ROWB + kk * 32 + boff;
            ldsm4(base, bhi[q]);
            ldsm4(base + PLANE, blo[q]);
        }
#pragma unroll
        for (int j = 0; j < 4; j++)
            mma16816(c[j], a, bhi[j >> 1][(j & 1) * 2], bhi[j >> 1][(j & 1) * 2 + 1]);
#pragma unroll
        for (int j = 0; j < 4; j++)
            mma16816_f16(clo[j], a, blo[j >> 1][(j & 1) * 2], blo[j >> 1][(j & 1) * 2 + 1]);
    }
}

__device__ __forceinline__ void zero_acc(float c[4][4], uint32_t clo[4][2]) {
#pragma unroll
    for (int b = 0; b < 4; b++) {
#pragma unroll
        for (int d = 0; d < 4; d++) c[b][d] = 0.f;
        clo[b][0] = 0u; clo[b][1] = 0u;
    }
}

__device__ __forceinline__ void merge_lo(float c[4][4], const uint32_t clo[4][2]) {
#pragma unroll
    for (int b = 0; b < 4; b++) {
        float2 f0 = __half22float2(*(const __half2*)&clo[b][0]);
        float2 f1 = __half22float2(*(const __half2*)&clo[b][1]);
        c[b][0] += f0.x; c[b][1] += f0.y;
        c[b][2] += f1.x; c[b][3] += f1.y;
    }
}

// ---------------------------------------------------------------------------
// Prep kernels
// ---------------------------------------------------------------------------
__device__ __forceinline__ void split16(float v, __half* hi, __half* lo) {
    __half h = __float2half_rn(v);
    *hi = h;
    *lo = __float2half_rn(v - __half2float(h));
}

__global__ void prep_w(const float* __restrict__ W_ih, const float* __restrict__ W_hh,
                       const float* __restrict__ b_ih, const float* __restrict__ b_hh) {
    int idx = blockIdx.x * 256 + threadIdx.x;
    if (idx < NGATE * KTOT) {
        int p = idx / KTOT, k = idx - p * KTOT;
        int j = p >> 2, g = p & 3;
        int srow = g * NH + j;
        float v = (k < NIN) ? W_ih[(size_t)srow * NIN + k]
                            : W_hh[(size_t)srow * NH + (k - NIN)];
        split16(v, &g_Whi[idx], &g_Wlo[idx]);
    }
    if (idx < NGATE) {
        int j = idx >> 2, g = idx & 3;
        g_bias[idx] = b_ih[g * NH + j] + b_hh[g * NH + j];
    }
}

__global__ void prep_wcls(const float* __restrict__ W_cls) {
    int idx = blockIdx.x * 256 + threadIdx.x;
    if (idx < NOUT * NH) split16(W_cls[idx], &g_Wchi[idx], &g_Wclo[idx]);
}

__global__ void prep_x(const float* __restrict__ input, const float* __restrict__ dtv) {
    int idx = blockIdx.x * 256 + threadIdx.x;
    if (idx < TT * BB * NIN) {
        int k = idx & (NIN - 1);
        int tb = idx >> 7;
        float v = (k < NIN - 1) ? input[(size_t)tb * (NIN - 1) + k] : dtv[tb];
        g_Xh[idx] = __float2half_rn(v);
    }
}

__global__ void prep_zero() {
    int idx = blockIdx.x * 256 + threadIdx.x;
    if (idx < 128) g_barA[idx] = 0;
    if (idx < BB * NH) g_Hh[idx] = __float2half_rn(0.0f);   // h_{-1}
}

// ---------------------------------------------------------------------------
// Persistent kernel: all 512 LSTM steps in one launch.
// grid (32 n-tiles, 4 m-groups) = 128 CTAs (1/SM), 256 threads (8 warps).
// W resident in smem; c in registers; per-m-group barriers; one sync/chunk via
// 5-buffer rotation; shfl epilogue (no gates smem round-trip); release-atomic
// arrive; h loads issued before x-chunk compute after the barrier.
// ---------------------------------------------------------------------------
__global__ void __launch_bounds__(256) persistent_step() {
    extern __shared__ char dyn[];
    __shared__ float s_bias[64];

    const uint32_t sb = smem_u32(dyn);                 // 5 A buffers
    const uint32_t wb = sb + NABUF * PLANE;            // resident W region
    const int tid = threadIdx.x, L = tid & 31, wid = tid >> 5;
    const int nt = blockIdx.x, mg = blockIdx.y, mbase = mg * 64;

    if (tid < 64) s_bias[tid] = g_bias[nt * 64 + tid];

    // --- resident W: 10 chunks x (hi,lo) planes, one cp.async group ---
#pragma unroll 4
    for (int i = 0; i < 40; i++) {
        int idx = tid + 256 * i;                       // 0..10239
        int pl = idx >> 9;                             // plane 0..19
        int rem = idx & 511, r = rem >> 3, ch = rem & 7;
        int s = pl >> 1, hl = pl & 1;
        const __half* src = (hl ? g_Wlo : g_Whi)
                          + (size_t)(nt * 64 + r) * KTOT + s * 64 + ch * 8;
        cpa16(wb + (uint32_t)pl * PLANE + r * ROWB + ch * 16, src);
    }
    CP_COMMIT();

    // --- x chunks 0,1 of t=0 into bufs 0,1 ---
    {
        const __half* xr = g_Xh + (size_t)mbase * NIN;
        load_A(sb,         tid, xr,      NIN);
        load_A(sb + PLANE, tid, xr + 64, NIN);
    }

    const int mwb = (wid & 3) * 16, nwb = (wid >> 2) * 32;
    const uint32_t aoff = (uint32_t)((((L >> 3) & 1) * 8 + (L & 7)) * ROWB + (L >> 4) * 16);
    const uint32_t boff = (uint32_t)(((L >> 4) * 8 + (L & 7)) * ROWB + ((L >> 3) & 1) * 16);

    asm volatile("cp.async.wait_group 0;" ::: "memory");
    __syncthreads();

    // bias for this thread's 4 (row,unit) cells: unit = nwb/4 + 2j + ((L&3)>>1)
    const int u0 = (L & 3) >> 1;
    float breg[4][4];
#pragma unroll
    for (int j = 0; j < 4; j++) {
        int ul = (nwb >> 2) + 2 * j + u0;
#pragma unroll
        for (int k = 0; k < 4; k++) breg[j][k] = s_bias[ul * 4 + k];
    }
    // cell-state mapping: thread owns (row = mwb + (L>>2) + 8*(L&1), unit ul_j)
    const int row_l = mwb + (L >> 2) + ((L & 1) << 3);
    float creg[4];
#pragma unroll
    for (int j = 0; j < 4; j++) creg[j] = 0.f;

    unsigned* barp = &g_barA[mg * 32];

    float c[4][4];
    uint32_t clo[4][2];

#pragma unroll 1
    for (int t = 0; t < TT; t++) {
        const __half* hrow = g_Hh + ((size_t)t * BB + mbase) * NH;

        // h chunks 2,3,4 -> bufs 2,3,4 (chunk s -> buf s%5)
        load_A(sb + 2 * PLANE, tid, hrow,       NH);
        load_A(sb + 3 * PLANE, tid, hrow + 64,  NH);
        load_A(sb + 4 * PLANE, tid, hrow + 128, NH);

        // chunks 0,1 (x, already synced) — overlaps the h-load latency
        zero_acc(c, clo);
        compute_chunk(sb,         wb,             mwb, nwb, aoff, boff, c, clo);
        compute_chunk(sb + PLANE, wb + 2 * PLANE, mwb, nwb, aoff, boff, c, clo);

#pragma unroll 1
        for (int s = 2; s < SK_CHUNKS; s++) {
            if (s <= 7)      asm volatile("cp.async.wait_group 2;" ::: "memory");
            else if (s == 8) asm volatile("cp.async.wait_group 1;" ::: "memory");
            else             asm volatile("cp.async.wait_group 0;" ::: "memory");
            __syncthreads();   // single sync per chunk: data visible + buffer free
            if (s <= 6) {      // load chunk s+3 (h cols (s+1)*64) into buf (s+3)%5
                load_A(sb + (uint32_t)((s + 3) % 5) * PLANE, tid, hrow + (s + 1) * 64, NH);
            }
            compute_chunk(sb + (uint32_t)(s % 5) * PLANE, wb + (uint32_t)s * 2 * PLANE,
                          mwb, nwb, aoff, boff, c, clo);
        }

        merge_lo(c, clo);

        // --- shfl epilogue: lane-pair exchange (even: i,f | odd: g,o) ---
#pragma unroll
        for (int j = 0; j < 4; j++) {
            float s0 = __shfl_xor_sync(0xffffffffu, (L & 1) ? c[j][0] : c[j][2], 1);
            float s1 = __shfl_xor_sync(0xffffffffu, (L & 1) ? c[j][1] : c[j][3], 1);
            float iv, fv, gg, ov;
            if (!(L & 1)) { iv = c[j][0]; fv = c[j][1]; gg = s0;       ov = s1;       }
            else          { iv = s0;       fv = s1;       gg = c[j][2]; ov = c[j][3]; }
            iv = fsigmoid(iv + breg[j][0]);
            fv = fsigmoid(fv + breg[j][1]);
            gg = ftanh(gg + breg[j][2]);
            ov = fsigmoid(ov + breg[j][3]);
            float cv = fv * creg[j] + iv * gg;
            creg[j] = cv;
            int ul = (nwb >> 2) + 2 * j + u0;
            *(__half*)(dyn + row_l * 32 + ul * 2) = __float2half_rn(ov * ftanh(cv));
        }
        __syncthreads();
        // coalesced h store: 64 rows x 16 units fp16 (stage in buf0 region)
        {
            int row = tid >> 2, seg = tid & 3;
            uint2 v = *(uint2*)(dyn + row * 32 + seg * 8);
            *(uint2*)(g_Hh + ((size_t)(t + 1) * BB + mbase + row) * NH + nt * 16 + seg * 4) = v;
        }
        __syncthreads();

        // arrive with release semantics (orders the h stores, no full membar)
        if (tid == 0)
            asm volatile("red.release.gpu.global.add.u32 [%0], %1;"
                         :: "l"(barp), "r"(1u) : "memory");

        if (t + 1 < TT) {
            // x(t+1) loads into bufs 0,1 (stage reads done; chunks 5,6 long consumed)
            const __half* xr = g_Xh + ((size_t)(t + 1) * BB + mbase) * NIN;
            load_A(sb,         tid, xr,      NIN);
            load_A(sb + PLANE, tid, xr + 64, NIN);

            // per-mg barrier: h_t rows of this m-group visible to its 32 CTAs
            if (tid == 0) {
                const unsigned target = 32u * (unsigned)(t + 1);
                unsigned v;
                unsigned long long guard = 0;
                do {
                    asm volatile("ld.acquire.gpu.global.u32 %0, [%1];" : "=r"(v) : "l"(barp));
                    if (v >= target) break;
                    if (++guard > 400000000ULL) __trap();   // loud abort on deadlock
                } while (true);
            }
            asm volatile("cp.async.wait_group 0;" ::: "memory");   // x arrived (hidden by spin)
            __syncthreads();
        }
    }
}

// ---------------------------------------------------------------------------
// Classifier: out[131072,64] = hs @ W_cls^T + b_cls. grid 2048 x 256 thr.
// Stage = A plane + Whi + Wlo planes, double-buffered (3 groups/stage).
// ---------------------------------------------------------------------------
__global__ void __launch_bounds__(256) cls_kernel(const float* __restrict__ b_cls,
                                                  float* __restrict__ out) {
    extern __shared__ char dyn[];
    __shared__ float s_bias[64];

    const uint32_t sb = smem_u32(dyn);
    const int tid = threadIdx.x, L = tid & 31, wid = tid >> 5;
    const size_t mb = (size_t)blockIdx.x * 64;

    if (tid < 64) s_bias[tid] = b_cls[tid];

    const __half* a0 = g_Hh + (BB + mb) * NH;   // hs rows (skip slot 0)

    load_A(sb,             tid, a0,     NH);
    load_A(sb + PLANE,     tid, g_Wchi, NH);
    load_A(sb + 2 * PLANE, tid, g_Wclo, NH);

    float c[4][4];
    uint32_t clo[4][2];
    zero_acc(c, clo);

    const int mwb = (wid & 3) * 16, nwb = (wid >> 2) * 32;
    const uint32_t aoff = (uint32_t)((((L >> 3) & 1) * 8 + (L & 7)) * ROWB + (L >> 4) * 16);
    const uint32_t boff = (uint32_t)(((L >> 4) * 8 + (L & 7)) * ROWB + ((L >> 3) & 1) * 16);

#pragma unroll 1
    for (int s = 0; s < CLS_CHUNKS; s++) {
        if (s + 1 < CLS_CHUNKS) {
            int sn = s + 1;
            uint32_t nb = sb + (sn & 1) * CLS_STAGE;
            load_A(nb,             tid, a0 + sn * 64,     NH);
            load_A(nb + PLANE,     tid, g_Wchi + sn * 64, NH);
            load_A(nb + 2 * PLANE, tid, g_Wclo + sn * 64, NH);
            asm volatile("cp.async.wait_group 3;" ::: "memory");
        } else {
            asm volatile("cp.async.wait_group 0;" ::: "memory");
        }
        __syncthreads();
        uint32_t base = sb + (s & 1) * CLS_STAGE;
        compute_chunk(base, base + PLANE, mwb, nwb, aoff, boff, c, clo);
        __syncthreads();
    }

    merge_lo(c, clo);

#pragma unroll
    for (int j = 0; j < 4; j++) {
        int row = mwb + (L >> 2);
        int col = nwb + j * 8 + 2 * (L & 3);
        float2 bb = *(const float2*)((const char*)s_bias + col * 4);
        float* op = out + (mb + row) * NOUT + col;
        *(float2*)op = make_float2(c[j][0] + bb.x, c[j][1] + bb.y);
        *(float2*)(op + 8 * NOUT) = make_float2(c[j][2] + bb.x, c[j][3] + bb.y);
    }
}

// ---------------------------------------------------------------------------
// Launch
// ---------------------------------------------------------------------------
extern "C" void kernel_launch(void* const* d_in, const int* in_sizes, int n_in,
                              void* d_out, int out_size) {
    const float* input = (const float*)d_in[0];
    const float* dtv   = (const float*)d_in[1];
    const float* W_ih  = (const float*)d_in[2];
    const float* W_hh  = (const float*)d_in[3];
    const float* b_ih  = (const float*)d_in[4];
    const float* b_hh  = (const float*)d_in[5];
    const float* W_cls = (const float*)d_in[6];
    const float* b_cls = (const float*)d_in[7];
    float* out = (float*)d_out;

    cudaFuncSetAttribute(persistent_step, cudaFuncAttributeMaxDynamicSharedMemorySize, PERS_SMEM);
    cudaFuncSetAttribute(cls_kernel, cudaFuncAttributeMaxDynamicSharedMemorySize, CLS_SMEM);

    prep_w<<<(NGATE * KTOT + 255) / 256, 256>>>(W_ih, W_hh, b_ih, b_hh);
    prep_wcls<<<(NOUT * NH + 255) / 256, 256>>>(W_cls);
    prep_x<<<(TT * BB * NIN + 255) / 256, 256>>>(input, dtv);
    prep_zero<<<(BB * NH + 255) / 256, 256>>>();

    persistent_step<<<dim3(32, 4), 256, PERS_SMEM>>>();
    cls_kernel<<<2048, 256, CLS_SMEM>>>(b_cls, out);
}